// round 10
// baseline (speedup 1.0000x reference)
#include <cuda_runtime.h>
#include <cuda_fp16.h>
#include <math.h>
#include <stdint.h>

#define B_   2
#define S_   2048
#define D_   512
#define H_   8
#define DK_  64
#define DFF_ 2048
#define L_   2
#define ROWS (B_*S_)   /* 4096 */

#define QKV_N  3072     /* qr|qi|kr|ki|kd|v */
#define QKV_LD 3072
#define AT_ST 72
#define ATTN_SMEM_BYTES (4 * 128 * AT_ST * 2)   /* 73728 */

// ---------------- scratch ----------------
__device__ float  g_zr  [ROWS * D_];
__device__ __half g_zrh [ROWS * D_];
__device__ __half g_acat[ROWS * 2 * D_];
__device__ __half g_qkvh[ROWS * QKV_LD];
__device__ __half g_ctxh[ROWS * D_];
__device__ float  g_t0  [ROWS * D_];
__device__ float  g_z1  [ROWS * D_];
__device__ __half g_z1h [ROWS * D_];
__device__ __half g_ffh [ROWS * DFF_];
__device__ __half g_b0h [QKV_N * 2 * D_];
__device__ __half g_b1h [QKV_N * D_];
#define WT2_PER_LAYER (D_*D_ + 2*D_*DFF_)
__device__ __half g_wth [L_ * WT2_PER_LAYER];

__device__ __forceinline__ uint32_t f22h(float a, float b) {
    __half2 h = __floats2half2_rn(a, b);
    return *(uint32_t*)&h;
}

__device__ __forceinline__ float rsqrt_fast(float x) {
    float y = __int_as_float(0x5f3759df - (__float_as_int(x) >> 1));
    y = y * (1.5f - 0.5f * x * y * y);
    y = y * (1.5f - 0.5f * x * y * y);
    return y;
}

// exp for |x| <= ~0.6: direct degree-5 Taylor
__device__ __forceinline__ float exp_poly(float x) {
    float p = 8.3333337e-3f;
    p = fmaf(p, x, 4.1666668e-2f);
    p = fmaf(p, x, 0.16666667f);
    p = fmaf(p, x, 0.5f);
    p = fmaf(p, x, 1.0f);
    p = fmaf(p, x, 1.0f);
    return p;
}

#define MMA_F16(acc, a, b0, b1) \
    asm volatile("mma.sync.aligned.m16n8k16.row.col.f32.f16.f16.f32 " \
        "{%0,%1,%2,%3}, {%4,%5,%6,%7}, {%8,%9}, {%0,%1,%2,%3};" \
        : "+f"((acc)[0]), "+f"((acc)[1]), "+f"((acc)[2]), "+f"((acc)[3]) \
        : "r"((a)[0]), "r"((a)[1]), "r"((a)[2]), "r"((a)[3]), "r"(b0), "r"(b1))

__device__ __forceinline__ void cp_async16(void* smem, const void* gmem) {
    uint32_t s = (uint32_t)__cvta_generic_to_shared(smem);
    asm volatile("cp.async.cg.shared.global [%0], [%1], 16;" :: "r"(s), "l"(gmem));
}
#define CP_COMMIT() asm volatile("cp.async.commit_group;" ::: "memory")
#define CP_WAIT0()  asm volatile("cp.async.wait_group 0;"  ::: "memory")

__device__ __forceinline__ void ldmx4(uint32_t* r, uint32_t addr) {
    asm volatile("ldmatrix.sync.aligned.m8n8.x4.shared.b16 {%0,%1,%2,%3}, [%4];"
        : "=r"(r[0]), "=r"(r[1]), "=r"(r[2]), "=r"(r[3]) : "r"(addr));
}
__device__ __forceinline__ void ldmx2(uint32_t& r0, uint32_t& r1, uint32_t addr) {
    asm volatile("ldmatrix.sync.aligned.m8n8.x2.shared.b16 {%0,%1}, [%2];"
        : "=r"(r0), "=r"(r1) : "r"(addr));
}
__device__ __forceinline__ void ldmx2t(uint32_t& r0, uint32_t& r1, uint32_t addr) {
    asm volatile("ldmatrix.sync.aligned.m8n8.x2.trans.shared.b16 {%0,%1}, [%2];"
        : "=r"(r0), "=r"(r1) : "r"(addr));
}

__device__ __forceinline__ uint32_t hadd2u(uint32_t a, uint32_t b) {
    __half2 r = __hadd2(*(__half2*)&a, *(__half2*)&b);
    return *(uint32_t*)&r;
}

// ---------------- all-fp16 pipelined tensor-core GEMM ----------------
__global__ void __launch_bounds__(256) tc_gemm_h_kernel(
    const __half* __restrict__ A, const __half* __restrict__ Bt, void* __restrict__ C,
    int M, int N, int K, const float* __restrict__ bias, int relu, int out_half)
{
    __shared__ __half As[2][128][40];
    __shared__ __half Bs[2][128][40];

    const int tid  = threadIdx.x;
    const int wid  = tid >> 5, lane = tid & 31;
    const int gid  = lane >> 2, tig = lane & 3;
    const int wy   = wid >> 2, wx = wid & 3;
    const int bm   = blockIdx.y, bn = blockIdx.x;

    const __half* Ab = A  + (size_t)bm * 128 * K;
    const __half* Bb = Bt + (size_t)bn * 128 * K;

    const int lr = tid >> 2;
    const int c8 = (tid & 3) * 8;

    const uint32_t As_sh = (uint32_t)__cvta_generic_to_shared(As);
    const uint32_t Bs_sh = (uint32_t)__cvta_generic_to_shared(Bs);
    const uint32_t a_lo = (uint32_t)(lane & 15) * 40 + ((lane >> 4) << 3);
    const uint32_t b_lo = (uint32_t)(lane & 7)  * 40 + (lane & 8);

    float acc[4][4][4];
    #pragma unroll
    for (int i = 0; i < 4; i++)
        #pragma unroll
        for (int j = 0; j < 4; j++)
            #pragma unroll
            for (int r = 0; r < 4; r++) acc[i][j][r] = 0.f;

    const int nch = K >> 5;

    {
        const __half* a0 = Ab + (size_t)lr * K + c8;
        const __half* b0 = Bb + (size_t)lr * K + c8;
        cp_async16(&As[0][lr     ][c8], a0);
        cp_async16(&As[0][lr + 64][c8], a0 + (size_t)64 * K);
        cp_async16(&Bs[0][lr     ][c8], b0);
        cp_async16(&Bs[0][lr + 64][c8], b0 + (size_t)64 * K);
        CP_COMMIT();
    }

    for (int c = 0; c < nch; c++) {
        CP_WAIT0();
        __syncthreads();
        if (c + 1 < nch) {
            const int sn = (c + 1) & 1;
            const int kg = (c + 1) * 32 + c8;
            const __half* a0 = Ab + (size_t)lr * K + kg;
            const __half* b0 = Bb + (size_t)lr * K + kg;
            cp_async16(&As[sn][lr     ][c8], a0);
            cp_async16(&As[sn][lr + 64][c8], a0 + (size_t)64 * K);
            cp_async16(&Bs[sn][lr     ][c8], b0);
            cp_async16(&Bs[sn][lr + 64][c8], b0 + (size_t)64 * K);
            CP_COMMIT();
        }
        const int s = c & 1;
        const uint32_t abase = As_sh + (uint32_t)s * 128 * 40 * 2;
        const uint32_t bbase = Bs_sh + (uint32_t)s * 128 * 40 * 2;
        #pragma unroll
        for (int ks = 0; ks < 2; ks++) {
            uint32_t af[4][4];
            #pragma unroll
            for (int mf = 0; mf < 4; mf++)
                ldmx4(af[mf], abase + ((uint32_t)(wy*64 + mf*16) * 40 + ks*16 + a_lo) * 2);
            uint32_t bf[4][2];
            #pragma unroll
            for (int nf = 0; nf < 4; nf++)
                ldmx2(bf[nf][0], bf[nf][1],
                      bbase + ((uint32_t)(wx*32 + nf*8) * 40 + ks*16 + b_lo) * 2);
            #pragma unroll
            for (int mf = 0; mf < 4; mf++)
                #pragma unroll
                for (int nf = 0; nf < 4; nf++)
                    MMA_F16(acc[mf][nf], af[mf], bf[nf][0], bf[nf][1]);
        }
        __syncthreads();
    }

    float2 bsv[4];
    if (bias) {
        #pragma unroll
        for (int nf = 0; nf < 4; nf++) {
            const int col = bn * 128 + wx * 32 + nf * 8 + tig * 2;
            bsv[nf] = *(const float2*)(bias + col);
        }
    }
    #pragma unroll
    for (int mf = 0; mf < 4; mf++) {
        const int row = bm * 128 + wy * 64 + mf * 16 + gid;
        #pragma unroll
        for (int nf = 0; nf < 4; nf++) {
            const int col = bn * 128 + wx * 32 + nf * 8 + tig * 2;
            #pragma unroll
            for (int half = 0; half < 2; half++) {
                const int r = row + half * 8;
                float vx = acc[mf][nf][half*2 + 0];
                float vy = acc[mf][nf][half*2 + 1];
                if (bias) { vx += bsv[nf].x; vy += bsv[nf].y; }
                if (relu) { vx = fmaxf(vx, 0.f); vy = fmaxf(vy, 0.f); }
                if (out_half) {
                    *(uint32_t*)((__half*)C + (size_t)r * N + col) = f22h(vx, vy);
                } else {
                    *(float2*)((float*)C + (size_t)r * N + col) = make_float2(vx, vy);
                }
            }
        }
    }
}

// ---------------- weight transpose (fp32 -> fp16) ----------------
__global__ void __launch_bounds__(256) transpose_h_kernel(
    const float* __restrict__ in, __half* __restrict__ out, int R, int Cc)
{
    __shared__ float t[32][33];
    int r0 = blockIdx.y * 32, c0 = blockIdx.x * 32;
    #pragma unroll
    for (int i = threadIdx.y; i < 32; i += 8)
        t[i][threadIdx.x] = in[(size_t)(r0 + i) * Cc + c0 + threadIdx.x];
    __syncthreads();
    #pragma unroll
    for (int i = threadIdx.y; i < 32; i += 8)
        out[(size_t)(c0 + i) * R + r0 + threadIdx.x] = __float2half_rn(t[threadIdx.x][i]);
}

// ---------------- fused QKV weight assembly (6 blocks incl. kd = kr - ki) ----
__global__ void __launch_bounds__(256) assemble_qkvB_kernel(
    const float* __restrict__ Wqr, const float* __restrict__ Wqi,
    const float* __restrict__ Wkr, const float* __restrict__ Wki,
    const float* __restrict__ Wv,  __half* __restrict__ out, int Kfull)
{
    __shared__ float t[32][33];
    const int k0 = blockIdx.x * 32, n0 = blockIdx.y * 32;
    const int blk  = n0 >> 9;        // 0:qr 1:qi 2:kr 3:ki 4:kd 5:v
    const int half = k0 >> 9;
    const int ks   = k0 & 511;
    const int ns   = n0 & 511;

    const float *sA = nullptr, *sB = nullptr;
    float ca = 1.f, cb = 0.f;
    if      (blk == 0) { if (half == 0) sA = Wqr; else { sA = Wqi; ca = -1.f; } }
    else if (blk == 1) { if (half == 0) sA = Wqi; else   sA = Wqr; }
    else if (blk == 2) { if (half == 0) sA = Wkr; else { sA = Wki; ca = -1.f; } }
    else if (blk == 3) { if (half == 0) sA = Wki; else   sA = Wkr; }
    else if (blk == 4) {
        if (half == 0) { sA = Wkr; ca =  1.f; sB = Wki; cb = -1.f; }   // kd = kr - ki
        else           { sA = Wki; ca = -1.f; sB = Wkr; cb = -1.f; }
    }
    else               { if (half == 0) sA = Wv; }

    #pragma unroll
    for (int i = threadIdx.y; i < 32; i += 8) {
        size_t idx = (size_t)(ks + i) * 512 + ns + threadIdx.x;
        float v = sA ? ca * sA[idx] : 0.f;
        if (sB) v = fmaf(cb, sB[idx], v);
        t[i][threadIdx.x] = v;
    }
    __syncthreads();
    #pragma unroll
    for (int i = threadIdx.y; i < 32; i += 8)
        out[(size_t)(n0 + i) * Kfull + k0 + threadIdx.x] =
            __float2half_rn(t[threadIdx.x][i]);
}

// ---------------- embedding / positional ----------------
__global__ void __launch_bounds__(128) embed_kernel(
    const int* __restrict__ tok, const float* __restrict__ emb,
    float* __restrict__ zr, __half* __restrict__ acat)
{
    int row = blockIdx.x;
    int t = tok[row];
    int c4 = threadIdx.x * 4;
    float4 v = *(const float4*)(emb + (size_t)t * D_ + c4);
    *(float4*)(zr + (size_t)row * D_ + c4) = v;
    *(uint2*)(acat + (size_t)row * 2 * D_ + c4) =
        make_uint2(f22h(v.x, v.y), f22h(v.z, v.w));
}

__global__ void __launch_bounds__(256) posimag_kernel(__half* __restrict__ acat)
{
    int s = blockIdx.x;
    int j = threadIdx.x;
    float freq = expf(-((float)j * (1.0f/256.0f)) * 9.2103403719761836f);
    float val = sinf((float)s * freq);
    uint32_t vv = f22h(val, val);
    int d = D_ + j * 2;
    *(uint32_t*)(acat + (size_t)(0 * S_ + s) * 2 * D_ + d) = vv;
    *(uint32_t*)(acat + (size_t)(1 * S_ + s) * 2 * D_ + d) = vv;
}

// ---------------- fp16 TC complex-hybrid flash attention (Karatsuba scores) ----
// 3-mult complex scores: m1=Qr*Kr, m2=Qi*Ki, m3=(Qr+Qi)*(Kr-Ki);
// sr = m1+m2, si = m3 - m1 + m2. Kd precomputed in the fused QKV buffer.
__global__ void __launch_bounds__(256) attn_tc_kernel(
    const __half* __restrict__ QKV, __half* __restrict__ Out)
{
    extern __shared__ __half smh[];
    __half (*bKr)[AT_ST] = (__half(*)[AT_ST])smh;   // 128 rows: 2 stages x 64
    __half (*bKi)[AT_ST] = bKr + 128;
    __half (*bKd)[AT_ST] = bKi + 128;
    __half (*bV )[AT_ST] = bKd + 128;

    const int q0 = blockIdx.x * 128;
    const int h  = blockIdx.y;
    const int b  = blockIdx.z;
    const int tid  = threadIdx.x;
    const int wid  = tid >> 5, lane = tid & 31;
    const int gid  = lane >> 2, tig = lane & 3;
    const int wrow = wid * 16;
    const size_t baseq = ((size_t)b * S_) * QKV_LD + (size_t)h * DK_;
    const size_t baseo = ((size_t)b * S_) * D_     + (size_t)h * DK_;

    const uint32_t kr_sh = (uint32_t)__cvta_generic_to_shared(bKr);
    const uint32_t ki_sh = (uint32_t)__cvta_generic_to_shared(bKi);
    const uint32_t kd_sh = (uint32_t)__cvta_generic_to_shared(bKd);
    const uint32_t v_sh  = (uint32_t)__cvta_generic_to_shared(bV);

    // ---- stage Q (qr into bKr rows 0..127, qi into bKi rows 0..127) ----
    for (int i = tid; i < 128*8; i += 256) {
        int r = i >> 3, c8 = (i & 7) * 8;
        const __half* qrow = QKV + baseq + (size_t)(q0 + r) * QKV_LD + c8;
        *(uint4*)&bKr[r][c8] = *(const uint4*)(qrow);
        *(uint4*)&bKi[r][c8] = *(const uint4*)(qrow + 512);
    }
    __syncthreads();

    uint32_t aQr[4][4], aQi[4][4], aQs[4][4];
    {
        const uint32_t ro = ((uint32_t)(wrow + (lane & 15)) * AT_ST + ((lane >> 4) << 3)) * 2;
        #pragma unroll
        for (int k = 0; k < 4; k++) {
            ldmx4(aQr[k], kr_sh + ro + k * 32);
            ldmx4(aQi[k], ki_sh + ro + k * 32);
            #pragma unroll
            for (int i = 0; i < 4; i++) aQs[k][i] = hadd2u(aQr[k][i], aQi[k][i]);
        }
    }
    __syncthreads();

    float o[8][4];
    #pragma unroll
    for (int n = 0; n < 8; n++)
        #pragma unroll
        for (int e = 0; e < 4; e++) o[n][e] = 0.f;
    float l0 = 0.f, l1 = 0.f;

    const uint32_t kb_lo = (uint32_t)(lane & 7) * AT_ST + (lane & 8);
    const uint32_t vb_lo = (uint32_t)(lane & 15) * AT_ST;

    // prologue: stage tile 0 into stage 0
    {
        for (int i = tid; i < 64*8; i += 256) {
            int r = i >> 3, c8 = (i & 7) * 8;
            const __half* krow = QKV + baseq + (size_t)r * QKV_LD + c8;
            cp_async16(&bKr[r][c8], krow + 1024);
            cp_async16(&bKi[r][c8], krow + 1536);
            cp_async16(&bKd[r][c8], krow + 2048);
            cp_async16(&bV [r][c8], krow + 2560);
        }
        CP_COMMIT();
    }

    const int NT = S_ / 64;
    for (int ti = 0; ti < NT; ti++) {
        CP_WAIT0();
        __syncthreads();
        if (ti + 1 < NT) {
            const int sn = (ti + 1) & 1;
            const int kt = (ti + 1) * 64;
            for (int i = tid; i < 64*8; i += 256) {
                int r = i >> 3, c8 = (i & 7) * 8;
                const __half* krow = QKV + baseq + (size_t)(kt + r) * QKV_LD + c8;
                cp_async16(&bKr[sn*64 + r][c8], krow + 1024);
                cp_async16(&bKi[sn*64 + r][c8], krow + 1536);
                cp_async16(&bKd[sn*64 + r][c8], krow + 2048);
                cp_async16(&bV [sn*64 + r][c8], krow + 2560);
            }
            CP_COMMIT();
        }
        const int s = ti & 1;
        const uint32_t soff = (uint32_t)(s * 64) * AT_ST * 2;

        // ---- scores: 3 MMA chains (m1, m2, m3) ----
        float mA[8][4], mB[8][4], mC[8][4];
        #pragma unroll
        for (int n = 0; n < 8; n++)
            #pragma unroll
            for (int e = 0; e < 4; e++) { mA[n][e] = 0.f; mB[n][e] = 0.f; mC[n][e] = 0.f; }

        #pragma unroll
        for (int k = 0; k < 4; k++) {
            #pragma unroll
            for (int n = 0; n < 8; n++) {
                const uint32_t off = soff + ((uint32_t)(n * 8) * AT_ST + k * 16 + kb_lo) * 2;
                uint32_t b0r, b1r, b0i, b1i, b0d, b1d;
                ldmx2(b0r, b1r, kr_sh + off);
                ldmx2(b0i, b1i, ki_sh + off);
                ldmx2(b0d, b1d, kd_sh + off);
                MMA_F16(mA[n], aQr[k], b0r, b1r);
                MMA_F16(mB[n], aQi[k], b0i, b1i);
                MMA_F16(mC[n], aQs[k], b0d, b1d);
            }
        }

        // ---- hybrid score -> p (p stored into mA) ----
        float psum0 = 0.f, psum1 = 0.f;
        #pragma unroll
        for (int n = 0; n < 8; n++) {
            #pragma unroll
            for (int e = 0; e < 4; e++) {
                float a = mA[n][e] + mB[n][e];
                float c = mC[n][e] - mA[n][e] + mB[n][e];
                float m2 = fmaf(a, a, c * c);
                float y  = rsqrt_fast(m2);
                float sc = y * fmaf(0.015625f, m2, 0.0375f * a);
                sc = (m2 == 0.f) ? 0.0375f : sc;
                float p = exp_poly(sc);
                mA[n][e] = p;
                if (e < 2) psum0 += p; else psum1 += p;
            }
        }
        psum0 += __shfl_xor_sync(0xffffffffu, psum0, 1);
        psum0 += __shfl_xor_sync(0xffffffffu, psum0, 2);
        psum1 += __shfl_xor_sync(0xffffffffu, psum1, 1);
        psum1 += __shfl_xor_sync(0xffffffffu, psum1, 2);
        l0 += psum0; l1 += psum1;

        // ---- PV: P in registers; V fragments via ldmatrix.trans ----
        #pragma unroll
        for (int kc = 0; kc < 4; kc++) {
            uint32_t ap[4];
            ap[0] = f22h(mA[2*kc  ][0], mA[2*kc  ][1]);
            ap[1] = f22h(mA[2*kc  ][2], mA[2*kc  ][3]);
            ap[2] = f22h(mA[2*kc+1][0], mA[2*kc+1][1]);
            ap[3] = f22h(mA[2*kc+1][2], mA[2*kc+1][3]);
            #pragma unroll
            for (int n = 0; n < 8; n++) {
                const uint32_t off = soff + ((uint32_t)(kc * 16) * AT_ST + n * 8 + vb_lo) * 2;
                uint32_t b0, b1;
                ldmx2t(b0, b1, v_sh + off);
                MMA_F16(o[n], ap, b0, b1);
            }
        }
    }

    const float inv0 = 1.0f / l0;
    const float inv1 = 1.0f / l1;
    #pragma unroll
    for (int n = 0; n < 8; n++) {
        const int col = n * 8 + 2 * tig;
        *(uint32_t*)(Out + baseo + (size_t)(q0 + wrow + gid    ) * D_ + col) =
            f22h(o[n][0] * inv0, o[n][1] * inv0);
        *(uint32_t*)(Out + baseo + (size_t)(q0 + wrow + gid + 8) * D_ + col) =
            f22h(o[n][2] * inv1, o[n][3] * inv1);
    }
}

// ---------------- fused residual + layernorm ----------------
__global__ void __launch_bounds__(128) ln_res_kernel(
    const float* __restrict__ x, const float* __restrict__ r,
    const float* __restrict__ g, const float* __restrict__ be,
    float* __restrict__ outf, __half* __restrict__ outh)
{
    __shared__ float red[8];
    int row = blockIdx.x, tid = threadIdx.x;
    float4 xv = *(const float4*)(x + (size_t)row * D_ + tid * 4);
    float4 rv = *(const float4*)(r + (size_t)row * D_ + tid * 4);
    float v0 = xv.x + rv.x, v1 = xv.y + rv.y, v2 = xv.z + rv.z, v3 = xv.w + rv.w;
    float s  = v0 + v1 + v2 + v3;
    float s2 = v0*v0 + v1*v1 + v2*v2 + v3*v3;
    #pragma unroll
    for (int o = 16; o >= 1; o >>= 1) {
        s  += __shfl_xor_sync(0xffffffffu, s,  o);
        s2 += __shfl_xor_sync(0xffffffffu, s2, o);
    }
    int warp = tid >> 5, lane = tid & 31;
    if (lane == 0) { red[warp] = s; red[4 + warp] = s2; }
    __syncthreads();
    s  = red[0] + red[1] + red[2] + red[3];
    s2 = red[4] + red[5] + red[6] + red[7];
    float mu  = s  * (1.0f / D_);
    float var = s2 * (1.0f / D_) - mu * mu;
    float inv = rsqrtf(var + 1e-5f);
    float4 gv = *(const float4*)(g  + tid * 4);
    float4 bv = *(const float4*)(be + tid * 4);
    float4 o4;
    o4.x = (v0 - mu) * inv * gv.x + bv.x;
    o4.y = (v1 - mu) * inv * gv.y + bv.y;
    o4.z = (v2 - mu) * inv * gv.z + bv.z;
    o4.w = (v3 - mu) * inv * gv.w + bv.w;
    *(float4*)(outf + (size_t)row * D_ + tid * 4) = o4;
    *(uint2*)(outh + (size_t)row * D_ + tid * 4) =
        make_uint2(f22h(o4.x, o4.y), f22h(o4.z, o4.w));
}

// ---------------- classification head ----------------
__global__ void __launch_bounds__(256) head_kernel(
    const float* __restrict__ z, const float* __restrict__ w,
    const float* __restrict__ hb, float* __restrict__ out)
{
    int warp = threadIdx.x >> 5, lane = threadIdx.x & 31;
    int row = blockIdx.x * 8 + warp;
    const float* zr = z + (size_t)row * D_;
    float s0 = 0.f, s1 = 0.f;
    for (int d = lane; d < D_; d += 32) {
        float zv = zr[d];
        s0 += zv * w[d*2 + 0];
        s1 += zv * w[d*2 + 1];
    }
    #pragma unroll
    for (int o = 16; o >= 1; o >>= 1) {
        s0 += __shfl_xor_sync(0xffffffffu, s0, o);
        s1 += __shfl_xor_sync(0xffffffffu, s1, o);
    }
    if (lane == 0) {
        out[row*2 + 0] = s0 + hb[0];
        out[row*2 + 1] = s1 + hb[1];
    }
}

// ---------------- host-side orchestration ----------------
static inline void launch_gemm(const __half* A, const __half* Bt, void* C,
                               int M, int N, int K, const float* bias, int relu,
                               int out_half)
{
    dim3 grid(N / 128, M / 128);
    tc_gemm_h_kernel<<<grid, 256>>>(A, Bt, C, M, N, K, bias, relu, out_half);
}

static inline void launch_transpose(const float* in, __half* out, int R, int Cc)
{
    dim3 grid(Cc / 32, R / 32);
    transpose_h_kernel<<<grid, dim3(32, 8)>>>(in, out, R, Cc);
}

extern "C" void kernel_launch(void* const* d_in, const int* in_sizes, int n_in,
                              void* d_out, int out_size)
{
    (void)in_sizes; (void)n_in; (void)out_size;
    const int*   tokens = (const int*)  d_in[0];
    const float* embed  = (const float*)d_in[1];
    const float* Wqr = (const float*)d_in[2];
    const float* Wqi = (const float*)d_in[3];
    const float* Wkr = (const float*)d_in[4];
    const float* Wki = (const float*)d_in[5];
    const float* Wv  = (const float*)d_in[6];
    const float* Wo  = (const float*)d_in[7];
    const float* bo  = (const float*)d_in[8];
    const float* W1  = (const float*)d_in[9];
    const float* b1  = (const float*)d_in[10];
    const float* W2  = (const float*)d_in[11];
    const float* b2  = (const float*)d_in[12];
    const float* g1  = (const float*)d_in[13];
    const float* be1 = (const float*)d_in[14];
    const float* g2  = (const float*)d_in[15];
    const float* be2 = (const float*)d_in[16];
    const float* hw  = (const float*)d_in[17];
    const float* hb  = (const float*)d_in[18];
    float* out = (float*)d_out;

    float *zr,*t0,*z1;
    __half *zrh,*acat,*qkvh,*ctxh,*z1h,*ffh,*b0h,*b1h,*wth;
    cudaGetSymbolAddress((void**)&zr,   g_zr);
    cudaGetSymbolAddress((void**)&zrh,  g_zrh);
    cudaGetSymbolAddress((void**)&acat, g_acat);
    cudaGetSymbolAddress((void**)&qkvh, g_qkvh);
    cudaGetSymbolAddress((void**)&ctxh, g_ctxh);
    cudaGetSymbolAddress((void**)&t0,   g_t0);
    cudaGetSymbolAddress((void**)&z1,   g_z1);
    cudaGetSymbolAddress((void**)&z1h,  g_z1h);
    cudaGetSymbolAddress((void**)&ffh,  g_ffh);
    cudaGetSymbolAddress((void**)&b0h,  g_b0h);
    cudaGetSymbolAddress((void**)&b1h,  g_b1h);
    cudaGetSymbolAddress((void**)&wth,  g_wth);

    cudaFuncSetAttribute(attn_tc_kernel, cudaFuncAttributeMaxDynamicSharedMemorySize,
                         ATTN_SMEM_BYTES);

    embed_kernel<<<ROWS, 128>>>(tokens, embed, zr, acat);
    posimag_kernel<<<S_, 256>>>(acat);

    const size_t DD = (size_t)D_ * D_;
    const size_t DF = (size_t)D_ * DFF_;

    {
        dim3 g0(2 * D_ / 32, QKV_N / 32);
        assemble_qkvB_kernel<<<g0, dim3(32, 8)>>>(Wqr, Wqi, Wkr, Wki, Wv, b0h, 2 * D_);
        dim3 g1d(D_ / 32, QKV_N / 32);
        assemble_qkvB_kernel<<<g1d, dim3(32, 8)>>>(Wqr + DD, Wqi + DD, Wkr + DD,
                                                   Wki + DD, Wv + DD, b1h, D_);
    }
    for (int l = 0; l < L_; l++) {
        __half* base = wth + (size_t)l * WT2_PER_LAYER;
        launch_transpose(Wo + l*DD, base,           D_,   D_);
        launch_transpose(W1 + l*DF, base + DD,      D_,   DFF_);
        launch_transpose(W2 + l*DF, base + DD + DF, DFF_, D_);
    }

    for (int l = 0; l < L_; l++) {
        __half* base = wth + (size_t)l * WT2_PER_LAYER;
        const __half* woT  = base;
        const __half* w1T  = base + DD;
        const __half* w2T  = base + DD + DF;
        const float* bo_l  = bo  + (size_t)l * D_;
        const float* b1_l  = b1  + (size_t)l * DFF_;
        const float* b2_l  = b2  + (size_t)l * D_;
        const float* g1_l  = g1  + (size_t)l * D_;
        const float* be1_l = be1 + (size_t)l * D_;
        const float* g2_l  = g2  + (size_t)l * D_;
        const float* be2_l = be2 + (size_t)l * D_;

        if (l == 0)
            launch_gemm(acat, b0h, qkvh, ROWS, QKV_N, 2 * D_, nullptr, 0, 1);
        else
            launch_gemm(zrh, b1h, qkvh, ROWS, QKV_N, D_, nullptr, 0, 1);

        dim3 ag(S_ / 128, H_, B_);
        attn_tc_kernel<<<ag, 256, ATTN_SMEM_BYTES>>>(qkvh, ctxh);

        launch_gemm(ctxh, woT, t0, ROWS, D_, D_, bo_l, 0, 0);
        ln_res_kernel<<<ROWS, 128>>>(zr, t0, g1_l, be1_l, z1, z1h);
        launch_gemm(z1h, w1T, ffh, ROWS, DFF_, D_, b1_l, 1, 1);
        launch_gemm(ffh, w2T, t0, ROWS, D_, DFF_, b2_l, 0, 0);
        ln_res_kernel<<<ROWS, 128>>>(z1, t0, g2_l, be2_l, zr, zrh);
    }

    head_kernel<<<ROWS / 8, 256>>>(zr, hw, hb, out);
}

// round 11
// speedup vs baseline: 1.0426x; 1.0426x over previous
#include <cuda_runtime.h>
#include <cuda_fp16.h>
#include <math.h>
#include <stdint.h>

#define B_   2
#define S_   2048
#define D_   512
#define H_   8
#define DK_  64
#define DFF_ 2048
#define L_   2
#define ROWS (B_*S_)   /* 4096 */

#define QKV_N  2560
#define QKV_LD 2560
#define AT_ST 72
#define ATTN_SMEM_BYTES (6 * 64 * AT_ST * 2)   /* 55296 */

// ---------------- scratch ----------------
__device__ float  g_zr  [ROWS * D_];
__device__ __half g_zrh [ROWS * D_];
__device__ __half g_acat[ROWS * 2 * D_];
__device__ __half g_qkvh[ROWS * QKV_LD];
__device__ __half g_ctxh[ROWS * D_];
__device__ float  g_t0  [ROWS * D_];
__device__ float  g_z1  [ROWS * D_];
__device__ __half g_z1h [ROWS * D_];
__device__ __half g_ffh [ROWS * DFF_];
__device__ __half g_b0h [QKV_N * 2 * D_];
__device__ __half g_b1h [QKV_N * D_];
#define WT2_PER_LAYER (D_*D_ + 2*D_*DFF_)
__device__ __half g_wth [L_ * WT2_PER_LAYER];

__device__ __forceinline__ uint32_t f22h(float a, float b) {
    __half2 h = __floats2half2_rn(a, b);
    return *(uint32_t*)&h;
}

__device__ __forceinline__ float rsqrt_fast(float x) {
    float y = __int_as_float(0x5f3759df - (__float_as_int(x) >> 1));
    y = y * (1.5f - 0.5f * x * y * y);
    y = y * (1.5f - 0.5f * x * y * y);
    return y;
}

// exp for |x| <= ~0.6: direct degree-5 Taylor
__device__ __forceinline__ float exp_poly(float x) {
    float p = 8.3333337e-3f;
    p = fmaf(p, x, 4.1666668e-2f);
    p = fmaf(p, x, 0.16666667f);
    p = fmaf(p, x, 0.5f);
    p = fmaf(p, x, 1.0f);
    p = fmaf(p, x, 1.0f);
    return p;
}

#define MMA_F16(acc, a, b0, b1) \
    asm volatile("mma.sync.aligned.m16n8k16.row.col.f32.f16.f16.f32 " \
        "{%0,%1,%2,%3}, {%4,%5,%6,%7}, {%8,%9}, {%0,%1,%2,%3};" \
        : "+f"((acc)[0]), "+f"((acc)[1]), "+f"((acc)[2]), "+f"((acc)[3]) \
        : "r"((a)[0]), "r"((a)[1]), "r"((a)[2]), "r"((a)[3]), "r"(b0), "r"(b1))

__device__ __forceinline__ void cp_async16(void* smem, const void* gmem) {
    uint32_t s = (uint32_t)__cvta_generic_to_shared(smem);
    asm volatile("cp.async.cg.shared.global [%0], [%1], 16;" :: "r"(s), "l"(gmem));
}
#define CP_COMMIT() asm volatile("cp.async.commit_group;" ::: "memory")
#define CP_WAIT0()  asm volatile("cp.async.wait_group 0;"  ::: "memory")

__device__ __forceinline__ void ldmx4(uint32_t* r, uint32_t addr) {
    asm volatile("ldmatrix.sync.aligned.m8n8.x4.shared.b16 {%0,%1,%2,%3}, [%4];"
        : "=r"(r[0]), "=r"(r[1]), "=r"(r[2]), "=r"(r[3]) : "r"(addr));
}
__device__ __forceinline__ void ldmx4t(uint32_t* r, uint32_t addr) {
    asm volatile("ldmatrix.sync.aligned.m8n8.x4.trans.shared.b16 {%0,%1,%2,%3}, [%4];"
        : "=r"(r[0]), "=r"(r[1]), "=r"(r[2]), "=r"(r[3]) : "r"(addr));
}

// ---------------- all-fp16 pipelined tensor-core GEMM ----------------
__global__ void __launch_bounds__(256) tc_gemm_h_kernel(
    const __half* __restrict__ A, const __half* __restrict__ Bt, void* __restrict__ C,
    int M, int N, int K, const float* __restrict__ bias, int relu, int out_half)
{
    __shared__ __half As[2][128][40];
    __shared__ __half Bs[2][128][40];

    const int tid  = threadIdx.x;
    const int wid  = tid >> 5, lane = tid & 31;
    const int gid  = lane >> 2, tig = lane & 3;
    const int wy   = wid >> 2, wx = wid & 3;
    const int bm   = blockIdx.y, bn = blockIdx.x;

    const __half* Ab = A  + (size_t)bm * 128 * K;
    const __half* Bb = Bt + (size_t)bn * 128 * K;

    const int lr = tid >> 2;
    const int c8 = (tid & 3) * 8;

    const uint32_t As_sh = (uint32_t)__cvta_generic_to_shared(As);
    const uint32_t Bs_sh = (uint32_t)__cvta_generic_to_shared(Bs);
    // per-thread ldmatrix lane offsets (in halves)
    const uint32_t a_lo  = (uint32_t)(lane & 15) * 40 + ((lane >> 4) << 3);
    // x4 B layout: lanes {0-7,8-15}: rows n..n+7 cols {0,+8}; lanes {16-23,24-31}: rows n+8..n+15 cols {0,+8}
    const uint32_t b4_lo = ((uint32_t)(lane & 7) + ((lane >> 4) << 3)) * 40 + ((lane >> 3) & 1) * 8;

    float acc[4][4][4];
    #pragma unroll
    for (int i = 0; i < 4; i++)
        #pragma unroll
        for (int j = 0; j < 4; j++)
            #pragma unroll
            for (int r = 0; r < 4; r++) acc[i][j][r] = 0.f;

    const int nch = K >> 5;

    {
        const __half* a0 = Ab + (size_t)lr * K + c8;
        const __half* b0 = Bb + (size_t)lr * K + c8;
        cp_async16(&As[0][lr     ][c8], a0);
        cp_async16(&As[0][lr + 64][c8], a0 + (size_t)64 * K);
        cp_async16(&Bs[0][lr     ][c8], b0);
        cp_async16(&Bs[0][lr + 64][c8], b0 + (size_t)64 * K);
        CP_COMMIT();
    }

    for (int c = 0; c < nch; c++) {
        CP_WAIT0();
        __syncthreads();
        if (c + 1 < nch) {
            const int sn = (c + 1) & 1;
            const int kg = (c + 1) * 32 + c8;
            const __half* a0 = Ab + (size_t)lr * K + kg;
            const __half* b0 = Bb + (size_t)lr * K + kg;
            cp_async16(&As[sn][lr     ][c8], a0);
            cp_async16(&As[sn][lr + 64][c8], a0 + (size_t)64 * K);
            cp_async16(&Bs[sn][lr     ][c8], b0);
            cp_async16(&Bs[sn][lr + 64][c8], b0 + (size_t)64 * K);
            CP_COMMIT();
        }
        const int s = c & 1;
        const uint32_t abase = As_sh + (uint32_t)s * 128 * 40 * 2;
        const uint32_t bbase = Bs_sh + (uint32_t)s * 128 * 40 * 2;
        #pragma unroll
        for (int ks = 0; ks < 2; ks++) {
            uint32_t af[4][4];
            #pragma unroll
            for (int mf = 0; mf < 4; mf++)
                ldmx4(af[mf], abase + ((uint32_t)(wy*64 + mf*16) * 40 + ks*16 + a_lo) * 2);
            uint32_t bf[2][4];   // bf[p] = {b0_n, b1_n, b0_n+1, b1_n+1} for n-pair p
            #pragma unroll
            for (int p = 0; p < 2; p++)
                ldmx4(bf[p], bbase + ((uint32_t)(wx*32 + p*16) * 40 + ks*16 + b4_lo) * 2);
            #pragma unroll
            for (int mf = 0; mf < 4; mf++)
                #pragma unroll
                for (int p = 0; p < 2; p++) {
                    MMA_F16(acc[mf][2*p    ], af[mf], bf[p][0], bf[p][1]);
                    MMA_F16(acc[mf][2*p + 1], af[mf], bf[p][2], bf[p][3]);
                }
        }
        __syncthreads();
    }

    float2 bsv[4];
    if (bias) {
        #pragma unroll
        for (int nf = 0; nf < 4; nf++) {
            const int col = bn * 128 + wx * 32 + nf * 8 + tig * 2;
            bsv[nf] = *(const float2*)(bias + col);
        }
    }
    #pragma unroll
    for (int mf = 0; mf < 4; mf++) {
        const int row = bm * 128 + wy * 64 + mf * 16 + gid;
        #pragma unroll
        for (int nf = 0; nf < 4; nf++) {
            const int col = bn * 128 + wx * 32 + nf * 8 + tig * 2;
            #pragma unroll
            for (int half = 0; half < 2; half++) {
                const int r = row + half * 8;
                float vx = acc[mf][nf][half*2 + 0];
                float vy = acc[mf][nf][half*2 + 1];
                if (bias) { vx += bsv[nf].x; vy += bsv[nf].y; }
                if (relu) { vx = fmaxf(vx, 0.f); vy = fmaxf(vy, 0.f); }
                if (out_half) {
                    *(uint32_t*)((__half*)C + (size_t)r * N + col) = f22h(vx, vy);
                } else {
                    *(float2*)((float*)C + (size_t)r * N + col) = make_float2(vx, vy);
                }
            }
        }
    }
}

// ---------------- weight transpose (fp32 -> fp16) ----------------
__global__ void __launch_bounds__(256) transpose_h_kernel(
    const float* __restrict__ in, __half* __restrict__ out, int R, int Cc)
{
    __shared__ float t[32][33];
    int r0 = blockIdx.y * 32, c0 = blockIdx.x * 32;
    #pragma unroll
    for (int i = threadIdx.y; i < 32; i += 8)
        t[i][threadIdx.x] = in[(size_t)(r0 + i) * Cc + c0 + threadIdx.x];
    __syncthreads();
    #pragma unroll
    for (int i = threadIdx.y; i < 32; i += 8)
        out[(size_t)(c0 + i) * R + r0 + threadIdx.x] = __float2half_rn(t[threadIdx.x][i]);
}

// ---------------- fused QKV weight assembly (fp16 out) ----------------
__global__ void __launch_bounds__(256) assemble_qkvB_kernel(
    const float* __restrict__ Wqr, const float* __restrict__ Wqi,
    const float* __restrict__ Wkr, const float* __restrict__ Wki,
    const float* __restrict__ Wv,  __half* __restrict__ out, int Kfull)
{
    __shared__ float t[32][33];
    const int k0 = blockIdx.x * 32, n0 = blockIdx.y * 32;
    const int blk  = n0 >> 9;
    const int half = k0 >> 9;
    const int ks   = k0 & 511;
    const int ns   = n0 & 511;

    const float* src = Wv;
    float sign = 1.f;
    bool zero = false;
    if      (blk == 0) { if (half == 0) src = Wqr; else { src = Wqi; sign = -1.f; } }
    else if (blk == 1) { if (half == 0) src = Wqi; else   src = Wqr; }
    else if (blk == 2) { if (half == 0) src = Wkr; else { src = Wki; sign = -1.f; } }
    else if (blk == 3) { if (half == 0) src = Wki; else   src = Wkr; }
    else               { if (half == 0) src = Wv;  else   zero = true; }

    #pragma unroll
    for (int i = threadIdx.y; i < 32; i += 8)
        t[i][threadIdx.x] = zero ? 0.f : src[(size_t)(ks + i) * 512 + ns + threadIdx.x];
    __syncthreads();
    #pragma unroll
    for (int i = threadIdx.y; i < 32; i += 8)
        out[(size_t)(n0 + i) * Kfull + k0 + threadIdx.x] =
            __float2half_rn(sign * t[threadIdx.x][i]);
}

// ---------------- embedding / positional ----------------
__global__ void __launch_bounds__(128) embed_kernel(
    const int* __restrict__ tok, const float* __restrict__ emb,
    float* __restrict__ zr, __half* __restrict__ acat)
{
    int row = blockIdx.x;
    int t = tok[row];
    int c4 = threadIdx.x * 4;
    float4 v = *(const float4*)(emb + (size_t)t * D_ + c4);
    *(float4*)(zr + (size_t)row * D_ + c4) = v;
    *(uint2*)(acat + (size_t)row * 2 * D_ + c4) =
        make_uint2(f22h(v.x, v.y), f22h(v.z, v.w));
}

__global__ void __launch_bounds__(256) posimag_kernel(__half* __restrict__ acat)
{
    int s = blockIdx.x;
    int j = threadIdx.x;
    float freq = expf(-((float)j * (1.0f/256.0f)) * 9.2103403719761836f);
    float val = sinf((float)s * freq);
    uint32_t vv = f22h(val, val);
    int d = D_ + j * 2;
    *(uint32_t*)(acat + (size_t)(0 * S_ + s) * 2 * D_ + d) = vv;
    *(uint32_t*)(acat + (size_t)(1 * S_ + s) * 2 * D_ + d) = vv;
}

// ---------------- fp16 TC complex-hybrid flash attention ----------------
// 128 q-rows/CTA, 8 warps, cp.async double-buffered staging, x4 ldmatrix,
// P kept in registers.
__global__ void __launch_bounds__(256) attn_tc_kernel(
    const __half* __restrict__ QKV, __half* __restrict__ Out)
{
    extern __shared__ __half smh[];
    __half (*bKr)[AT_ST] = (__half(*)[AT_ST])smh;   // 128 rows: 2 stages x 64
    __half (*bKi)[AT_ST] = bKr + 128;
    __half (*bV )[AT_ST] = bKi + 128;

    const int q0 = blockIdx.x * 128;
    const int h  = blockIdx.y;
    const int b  = blockIdx.z;
    const int tid  = threadIdx.x;
    const int wid  = tid >> 5, lane = tid & 31;
    const int gid  = lane >> 2, tig = lane & 3;
    const int wrow = wid * 16;
    const size_t baseq = ((size_t)b * S_) * QKV_LD + (size_t)h * DK_;
    const size_t baseo = ((size_t)b * S_) * D_     + (size_t)h * DK_;

    const uint32_t kr_sh = (uint32_t)__cvta_generic_to_shared(bKr);
    const uint32_t ki_sh = (uint32_t)__cvta_generic_to_shared(bKi);
    const uint32_t v_sh  = (uint32_t)__cvta_generic_to_shared(bV);

    // ---- stage Q (qr into bKr[0..127], qi into bKi[0..127]) ----
    for (int i = tid; i < 128*8; i += 256) {
        int r = i >> 3, c8 = (i & 7) * 8;
        const __half* qrow = QKV + baseq + (size_t)(q0 + r) * QKV_LD + c8;
        *(uint4*)&bKr[r][c8] = *(const uint4*)(qrow);
        *(uint4*)&bKi[r][c8] = *(const uint4*)(qrow + 512);
    }
    __syncthreads();

    uint32_t aQr[4][4], aQi[4][4];
    {
        const uint32_t ro = ((uint32_t)(wrow + (lane & 15)) * AT_ST + ((lane >> 4) << 3)) * 2;
        #pragma unroll
        for (int k = 0; k < 4; k++) {
            ldmx4(aQr[k], kr_sh + ro + k * 32);
            ldmx4(aQi[k], ki_sh + ro + k * 32);
        }
    }
    __syncthreads();

    float o[8][4];
    #pragma unroll
    for (int n = 0; n < 8; n++)
        #pragma unroll
        for (int e = 0; e < 4; e++) o[n][e] = 0.f;
    float l0 = 0.f, l1 = 0.f;

    // x4 ldmatrix per-lane offsets (in halves)
    // B (non-trans): lanes{0-7,8-15}: rows n..n+7, cols {0,+8}; lanes{16-31}: rows n+8..n+15
    const uint32_t kb4_lo = ((uint32_t)(lane & 7) + ((lane >> 4) << 3)) * AT_ST
                          + ((lane >> 3) & 1) * 8;
    // V (trans): lanes 0-15: rows kc..kc+15 col n; lanes 16-31: same rows col n+8
    const uint32_t vb4_lo = (uint32_t)(lane & 15) * AT_ST + ((lane >> 4) << 3);

    // prologue: stage tile 0 into stage 0
    {
        for (int i = tid; i < 64*8; i += 256) {
            int r = i >> 3, c8 = (i & 7) * 8;
            const __half* krow = QKV + baseq + (size_t)r * QKV_LD + c8;
            cp_async16(&bKr[r][c8], krow + 1024);
            cp_async16(&bKi[r][c8], krow + 1536);
            cp_async16(&bV [r][c8], krow + 2048);
        }
        CP_COMMIT();
    }

    const int NT = S_ / 64;
    for (int ti = 0; ti < NT; ti++) {
        CP_WAIT0();
        __syncthreads();
        if (ti + 1 < NT) {
            const int sn = (ti + 1) & 1;
            const int kt = (ti + 1) * 64;
            for (int i = tid; i < 64*8; i += 256) {
                int r = i >> 3, c8 = (i & 7) * 8;
                const __half* krow = QKV + baseq + (size_t)(kt + r) * QKV_LD + c8;
                cp_async16(&bKr[sn*64 + r][c8], krow + 1024);
                cp_async16(&bKi[sn*64 + r][c8], krow + 1536);
                cp_async16(&bV [sn*64 + r][c8], krow + 2048);
            }
            CP_COMMIT();
        }
        const int s = ti & 1;
        const uint32_t soff = (uint32_t)(s * 64) * AT_ST * 2;

        // ---- scores ----
        float srf[8][4], sif[8][4];
        #pragma unroll
        for (int n = 0; n < 8; n++)
            #pragma unroll
            for (int e = 0; e < 4; e++) { srf[n][e] = 0.f; sif[n][e] = 0.f; }

        #pragma unroll
        for (int k = 0; k < 4; k++) {
            #pragma unroll
            for (int p = 0; p < 4; p++) {   // n-pairs: n = 2p, 2p+1
                const uint32_t off = soff + ((uint32_t)(p * 16) * AT_ST + k * 16 + kb4_lo) * 2;
                uint32_t br[4], bi[4];
                ldmx4(br, kr_sh + off);
                ldmx4(bi, ki_sh + off);
                MMA_F16(srf[2*p    ], aQr[k], br[0], br[1]);
                MMA_F16(srf[2*p    ], aQi[k], bi[0], bi[1]);
                MMA_F16(sif[2*p    ], aQi[k], br[0], br[1]);
                uint32_t x0 = bi[0] ^ 0x80008000u, x1 = bi[1] ^ 0x80008000u;
                MMA_F16(sif[2*p    ], aQr[k], x0, x1);
                MMA_F16(srf[2*p + 1], aQr[k], br[2], br[3]);
                MMA_F16(srf[2*p + 1], aQi[k], bi[2], bi[3]);
                MMA_F16(sif[2*p + 1], aQi[k], br[2], br[3]);
                uint32_t x2 = bi[2] ^ 0x80008000u, x3 = bi[3] ^ 0x80008000u;
                MMA_F16(sif[2*p + 1], aQr[k], x2, x3);
            }
        }

        // ---- hybrid score -> p ----
        float psum0 = 0.f, psum1 = 0.f;
        #pragma unroll
        for (int n = 0; n < 8; n++) {
            #pragma unroll
            for (int e = 0; e < 4; e++) {
                float a = srf[n][e], c = sif[n][e];
                float m2 = fmaf(a, a, c * c);
                float y  = rsqrt_fast(m2);
                float sc = y * fmaf(0.015625f, m2, 0.0375f * a);
                sc = (m2 == 0.f) ? 0.0375f : sc;
                float p = exp_poly(sc);
                srf[n][e] = p;
                if (e < 2) psum0 += p; else psum1 += p;
            }
        }
        psum0 += __shfl_xor_sync(0xffffffffu, psum0, 1);
        psum0 += __shfl_xor_sync(0xffffffffu, psum0, 2);
        psum1 += __shfl_xor_sync(0xffffffffu, psum1, 1);
        psum1 += __shfl_xor_sync(0xffffffffu, psum1, 2);
        l0 += psum0; l1 += psum1;

        // ---- PV: P in registers; V fragments via ldmatrix.x4.trans ----
        #pragma unroll
        for (int kc = 0; kc < 4; kc++) {
            uint32_t ap[4];
            ap[0] = f22h(srf[2*kc  ][0], srf[2*kc  ][1]);
            ap[1] = f22h(srf[2*kc  ][2], srf[2*kc  ][3]);
            ap[2] = f22h(srf[2*kc+1][0], srf[2*kc+1][1]);
            ap[3] = f22h(srf[2*kc+1][2], srf[2*kc+1][3]);
            #pragma unroll
            for (int p = 0; p < 4; p++) {   // n-pairs
                const uint32_t off = soff + ((uint32_t)(kc * 16) * AT_ST + p * 16 + vb4_lo) * 2;
                uint32_t bv[4];
                ldmx4t(bv, v_sh + off);
                MMA_F16(o[2*p    ], ap, bv[0], bv[1]);
                MMA_F16(o[2*p + 1], ap, bv[2], bv[3]);
            }
        }
    }

    const float inv0 = 1.0f / l0;
    const float inv1 = 1.0f / l1;
    #pragma unroll
    for (int n = 0; n < 8; n++) {
        const int col = n * 8 + 2 * tig;
        *(uint32_t*)(Out + baseo + (size_t)(q0 + wrow + gid    ) * D_ + col) =
            f22h(o[n][0] * inv0, o[n][1] * inv0);
        *(uint32_t*)(Out + baseo + (size_t)(q0 + wrow + gid + 8) * D_ + col) =
            f22h(o[n][2] * inv1, o[n][3] * inv1);
    }
}

// ---------------- fused residual + layernorm ----------------
__global__ void __launch_bounds__(128) ln_res_kernel(
    const float* __restrict__ x, const float* __restrict__ r,
    const float* __restrict__ g, const float* __restrict__ be,
    float* __restrict__ outf, __half* __restrict__ outh)
{
    __shared__ float red[8];
    int row = blockIdx.x, tid = threadIdx.x;
    float4 xv = *(const float4*)(x + (size_t)row * D_ + tid * 4);
    float4 rv = *(const float4*)(r + (size_t)row * D_ + tid * 4);
    float v0 = xv.x + rv.x, v1 = xv.y + rv.y, v2 = xv.z + rv.z, v3 = xv.w + rv.w;
    float s  = v0 + v1 + v2 + v3;
    float s2 = v0*v0 + v1*v1 + v2*v2 + v3*v3;
    #pragma unroll
    for (int o = 16; o >= 1; o >>= 1) {
        s  += __shfl_xor_sync(0xffffffffu, s,  o);
        s2 += __shfl_xor_sync(0xffffffffu, s2, o);
    }
    int warp = tid >> 5, lane = tid & 31;
    if (lane == 0) { red[warp] = s; red[4 + warp] = s2; }
    __syncthreads();
    s  = red[0] + red[1] + red[2] + red[3];
    s2 = red[4] + red[5] + red[6] + red[7];
    float mu  = s  * (1.0f / D_);
    float var = s2 * (1.0f / D_) - mu * mu;
    float inv = rsqrtf(var + 1e-5f);
    float4 gv = *(const float4*)(g  + tid * 4);
    float4 bv = *(const float4*)(be + tid * 4);
    float4 o4;
    o4.x = (v0 - mu) * inv * gv.x + bv.x;
    o4.y = (v1 - mu) * inv * gv.y + bv.y;
    o4.z = (v2 - mu) * inv * gv.z + bv.z;
    o4.w = (v3 - mu) * inv * gv.w + bv.w;
    *(float4*)(outf + (size_t)row * D_ + tid * 4) = o4;
    *(uint2*)(outh + (size_t)row * D_ + tid * 4) =
        make_uint2(f22h(o4.x, o4.y), f22h(o4.z, o4.w));
}

// ---------------- classification head ----------------
__global__ void __launch_bounds__(256) head_kernel(
    const float* __restrict__ z, const float* __restrict__ w,
    const float* __restrict__ hb, float* __restrict__ out)
{
    int warp = threadIdx.x >> 5, lane = threadIdx.x & 31;
    int row = blockIdx.x * 8 + warp;
    const float* zr = z + (size_t)row * D_;
    float s0 = 0.f, s1 = 0.f;
    for (int d = lane; d < D_; d += 32) {
        float zv = zr[d];
        s0 += zv * w[d*2 + 0];
        s1 += zv * w[d*2 + 1];
    }
    #pragma unroll
    for (int o = 16; o >= 1; o >>= 1) {
        s0 += __shfl_xor_sync(0xffffffffu, s0, o);
        s1 += __shfl_xor_sync(0xffffffffu, s1, o);
    }
    if (lane == 0) {
        out[row*2 + 0] = s0 + hb[0];
        out[row*2 + 1] = s1 + hb[1];
    }
}

// ---------------- host-side orchestration ----------------
static inline void launch_gemm(const __half* A, const __half* Bt, void* C,
                               int M, int N, int K, const float* bias, int relu,
                               int out_half)
{
    dim3 grid(N / 128, M / 128);
    tc_gemm_h_kernel<<<grid, 256>>>(A, Bt, C, M, N, K, bias, relu, out_half);
}

static inline void launch_transpose(const float* in, __half* out, int R, int Cc)
{
    dim3 grid(Cc / 32, R / 32);
    transpose_h_kernel<<<grid, dim3(32, 8)>>>(in, out, R, Cc);
}

extern "C" void kernel_launch(void* const* d_in, const int* in_sizes, int n_in,
                              void* d_out, int out_size)
{
    (void)in_sizes; (void)n_in; (void)out_size;
    const int*   tokens = (const int*)  d_in[0];
    const float* embed  = (const float*)d_in[1];
    const float* Wqr = (const float*)d_in[2];
    const float* Wqi = (const float*)d_in[3];
    const float* Wkr = (const float*)d_in[4];
    const float* Wki = (const float*)d_in[5];
    const float* Wv  = (const float*)d_in[6];
    const float* Wo  = (const float*)d_in[7];
    const float* bo  = (const float*)d_in[8];
    const float* W1  = (const float*)d_in[9];
    const float* b1  = (const float*)d_in[10];
    const float* W2  = (const float*)d_in[11];
    const float* b2  = (const float*)d_in[12];
    const float* g1  = (const float*)d_in[13];
    const float* be1 = (const float*)d_in[14];
    const float* g2  = (const float*)d_in[15];
    const float* be2 = (const float*)d_in[16];
    const float* hw  = (const float*)d_in[17];
    const float* hb  = (const float*)d_in[18];
    float* out = (float*)d_out;

    float *zr,*t0,*z1;
    __half *zrh,*acat,*qkvh,*ctxh,*z1h,*ffh,*b0h,*b1h,*wth;
    cudaGetSymbolAddress((void**)&zr,   g_zr);
    cudaGetSymbolAddress((void**)&zrh,  g_zrh);
    cudaGetSymbolAddress((void**)&acat, g_acat);
    cudaGetSymbolAddress((void**)&qkvh, g_qkvh);
    cudaGetSymbolAddress((void**)&ctxh, g_ctxh);
    cudaGetSymbolAddress((void**)&t0,   g_t0);
    cudaGetSymbolAddress((void**)&z1,   g_z1);
    cudaGetSymbolAddress((void**)&z1h,  g_z1h);
    cudaGetSymbolAddress((void**)&ffh,  g_ffh);
    cudaGetSymbolAddress((void**)&b0h,  g_b0h);
    cudaGetSymbolAddress((void**)&b1h,  g_b1h);
    cudaGetSymbolAddress((void**)&wth,  g_wth);

    cudaFuncSetAttribute(attn_tc_kernel, cudaFuncAttributeMaxDynamicSharedMemorySize,
                         ATTN_SMEM_BYTES);

    embed_kernel<<<ROWS, 128>>>(tokens, embed, zr, acat);
    posimag_kernel<<<S_, 256>>>(acat);

    const size_t DD = (size_t)D_ * D_;
    const size_t DF = (size_t)D_ * DFF_;

    {
        dim3 g0(2 * D_ / 32, QKV_N / 32);
        assemble_qkvB_kernel<<<g0, dim3(32, 8)>>>(Wqr, Wqi, Wkr, Wki, Wv, b0h, 2 * D_);
        dim3 g1d(D_ / 32, QKV_N / 32);
        assemble_qkvB_kernel<<<g1d, dim3(32, 8)>>>(Wqr + DD, Wqi + DD, Wkr + DD,
                                                   Wki + DD, Wv + DD, b1h, D_);
    }
    for (int l = 0; l < L_; l++) {
        __half* base = wth + (size_t)l * WT2_PER_LAYER;
        launch_transpose(Wo + l*DD, base,           D_,   D_);
        launch_transpose(W1 + l*DF, base + DD,      D_,   DFF_);
        launch_transpose(W2 + l*DF, base + DD + DF, DFF_, D_);
    }

    for (int l = 0; l < L_; l++) {
        __half* base = wth + (size_t)l * WT2_PER_LAYER;
        const __half* woT  = base;
        const __half* w1T  = base + DD;
        const __half* w2T  = base + DD + DF;
        const float* bo_l  = bo  + (size_t)l * D_;
        const float* b1_l  = b1  + (size_t)l * DFF_;
        const float* b2_l  = b2  + (size_t)l * D_;
        const float* g1_l  = g1  + (size_t)l * D_;
        const float* be1_l = be1 + (size_t)l * D_;
        const float* g2_l  = g2  + (size_t)l * D_;
        const float* be2_l = be2 + (size_t)l * D_;

        if (l == 0)
            launch_gemm(acat, b0h, qkvh, ROWS, QKV_N, 2 * D_, nullptr, 0, 1);
        else
            launch_gemm(zrh, b1h, qkvh, ROWS, QKV_N, D_, nullptr, 0, 1);

        dim3 ag(S_ / 128, H_, B_);
        attn_tc_kernel<<<ag, 256, ATTN_SMEM_BYTES>>>(qkvh, ctxh);

        launch_gemm(ctxh, woT, t0, ROWS, D_, D_, bo_l, 0, 0);
        ln_res_kernel<<<ROWS, 128>>>(zr, t0, g1_l, be1_l, z1, z1h);
        launch_gemm(z1h, w1T, ffh, ROWS, DFF_, D_, b1_l, 1, 1);
        launch_gemm(ffh, w2T, t0, ROWS, D_, DFF_, b2_l, 0, 0);
        ln_res_kernel<<<ROWS, 128>>>(z1, t0, g2_l, be2_l, zr, zrh);
    }

    head_kernel<<<ROWS / 8, 256>>>(zr, hw, hb, out);
}

// round 12
// speedup vs baseline: 1.0603x; 1.0169x over previous
#include <cuda_runtime.h>
#include <cuda_fp16.h>
#include <math.h>
#include <stdint.h>

#define B_   2
#define S_   2048
#define D_   512
#define H_   8
#define DK_  64
#define DFF_ 2048
#define L_   2
#define ROWS (B_*S_)   /* 4096 */

#define QKV_N  2560
#define QKV_LD 2560
#define AT_ST 72
#define ATTN_SMEM_BYTES (6 * 64 * AT_ST * 2)   /* 55296 */

// ---------------- scratch ----------------
__device__ float  g_zr  [ROWS * D_];
__device__ __half g_zrh [ROWS * D_];
__device__ __half g_acat[ROWS * 2 * D_];
__device__ __half g_qkvh[ROWS * QKV_LD];
__device__ __half g_ctxh[ROWS * D_];
__device__ float  g_t0  [ROWS * D_];
__device__ float  g_z1  [ROWS * D_];
__device__ __half g_z1h [ROWS * D_];
__device__ __half g_ffh [ROWS * DFF_];
__device__ __half g_b0h [QKV_N * 2 * D_];
__device__ __half g_b1h [QKV_N * D_];
#define WT2_PER_LAYER (D_*D_ + 2*D_*DFF_)
__device__ __half g_wth [L_ * WT2_PER_LAYER];

__device__ __forceinline__ uint32_t f22h(float a, float b) {
    __half2 h = __floats2half2_rn(a, b);
    return *(uint32_t*)&h;
}

#define MMA_F16(acc, a, b0, b1) \
    asm volatile("mma.sync.aligned.m16n8k16.row.col.f32.f16.f16.f32 " \
        "{%0,%1,%2,%3}, {%4,%5,%6,%7}, {%8,%9}, {%0,%1,%2,%3};" \
        : "+f"((acc)[0]), "+f"((acc)[1]), "+f"((acc)[2]), "+f"((acc)[3]) \
        : "r"((a)[0]), "r"((a)[1]), "r"((a)[2]), "r"((a)[3]), "r"(b0), "r"(b1))

__device__ __forceinline__ void cp_async16(void* smem, const void* gmem) {
    uint32_t s = (uint32_t)__cvta_generic_to_shared(smem);
    asm volatile("cp.async.cg.shared.global [%0], [%1], 16;" :: "r"(s), "l"(gmem));
}
#define CP_COMMIT() asm volatile("cp.async.commit_group;" ::: "memory")
#define CP_WAIT0()  asm volatile("cp.async.wait_group 0;"  ::: "memory")

__device__ __forceinline__ void ldmx4(uint32_t* r, uint32_t addr) {
    asm volatile("ldmatrix.sync.aligned.m8n8.x4.shared.b16 {%0,%1,%2,%3}, [%4];"
        : "=r"(r[0]), "=r"(r[1]), "=r"(r[2]), "=r"(r[3]) : "r"(addr));
}
__device__ __forceinline__ void ldmx4t(uint32_t* r, uint32_t addr) {
    asm volatile("ldmatrix.sync.aligned.m8n8.x4.trans.shared.b16 {%0,%1,%2,%3}, [%4];"
        : "=r"(r[0]), "=r"(r[1]), "=r"(r[2]), "=r"(r[3]) : "r"(addr));
}

// ---------------- all-fp16 pipelined tensor-core GEMM ----------------
__global__ void __launch_bounds__(256) tc_gemm_h_kernel(
    const __half* __restrict__ A, const __half* __restrict__ Bt, void* __restrict__ C,
    int M, int N, int K, const float* __restrict__ bias, int relu, int out_half)
{
    __shared__ __half As[2][128][40];
    __shared__ __half Bs[2][128][40];

    const int tid  = threadIdx.x;
    const int wid  = tid >> 5, lane = tid & 31;
    const int gid  = lane >> 2, tig = lane & 3;
    const int wy   = wid >> 2, wx = wid & 3;
    const int bm   = blockIdx.y, bn = blockIdx.x;

    const __half* Ab = A  + (size_t)bm * 128 * K;
    const __half* Bb = Bt + (size_t)bn * 128 * K;

    const int lr = tid >> 2;
    const int c8 = (tid & 3) * 8;

    const uint32_t As_sh = (uint32_t)__cvta_generic_to_shared(As);
    const uint32_t Bs_sh = (uint32_t)__cvta_generic_to_shared(Bs);
    const uint32_t a_lo  = (uint32_t)(lane & 15) * 40 + ((lane >> 4) << 3);
    const uint32_t b4_lo = ((uint32_t)(lane & 7) + ((lane >> 4) << 3)) * 40 + ((lane >> 3) & 1) * 8;

    float acc[4][4][4];
    #pragma unroll
    for (int i = 0; i < 4; i++)
        #pragma unroll
        for (int j = 0; j < 4; j++)
            #pragma unroll
            for (int r = 0; r < 4; r++) acc[i][j][r] = 0.f;

    const int nch = K >> 5;

    {
        const __half* a0 = Ab + (size_t)lr * K + c8;
        const __half* b0 = Bb + (size_t)lr * K + c8;
        cp_async16(&As[0][lr     ][c8], a0);
        cp_async16(&As[0][lr + 64][c8], a0 + (size_t)64 * K);
        cp_async16(&Bs[0][lr     ][c8], b0);
        cp_async16(&Bs[0][lr + 64][c8], b0 + (size_t)64 * K);
        CP_COMMIT();
    }

    for (int c = 0; c < nch; c++) {
        CP_WAIT0();
        __syncthreads();
        if (c + 1 < nch) {
            const int sn = (c + 1) & 1;
            const int kg = (c + 1) * 32 + c8;
            const __half* a0 = Ab + (size_t)lr * K + kg;
            const __half* b0 = Bb + (size_t)lr * K + kg;
            cp_async16(&As[sn][lr     ][c8], a0);
            cp_async16(&As[sn][lr + 64][c8], a0 + (size_t)64 * K);
            cp_async16(&Bs[sn][lr     ][c8], b0);
            cp_async16(&Bs[sn][lr + 64][c8], b0 + (size_t)64 * K);
            CP_COMMIT();
        }
        const int s = c & 1;
        const uint32_t abase = As_sh + (uint32_t)s * 128 * 40 * 2;
        const uint32_t bbase = Bs_sh + (uint32_t)s * 128 * 40 * 2;
        #pragma unroll
        for (int ks = 0; ks < 2; ks++) {
            uint32_t af[4][4];
            #pragma unroll
            for (int mf = 0; mf < 4; mf++)
                ldmx4(af[mf], abase + ((uint32_t)(wy*64 + mf*16) * 40 + ks*16 + a_lo) * 2);
            uint32_t bf[2][4];
            #pragma unroll
            for (int p = 0; p < 2; p++)
                ldmx4(bf[p], bbase + ((uint32_t)(wx*32 + p*16) * 40 + ks*16 + b4_lo) * 2);
            #pragma unroll
            for (int mf = 0; mf < 4; mf++)
                #pragma unroll
                for (int p = 0; p < 2; p++) {
                    MMA_F16(acc[mf][2*p    ], af[mf], bf[p][0], bf[p][1]);
                    MMA_F16(acc[mf][2*p + 1], af[mf], bf[p][2], bf[p][3]);
                }
        }
        __syncthreads();
    }

    float2 bsv[4];
    if (bias) {
        #pragma unroll
        for (int nf = 0; nf < 4; nf++) {
            const int col = bn * 128 + wx * 32 + nf * 8 + tig * 2;
            bsv[nf] = *(const float2*)(bias + col);
        }
    }
    #pragma unroll
    for (int mf = 0; mf < 4; mf++) {
        const int row = bm * 128 + wy * 64 + mf * 16 + gid;
        #pragma unroll
        for (int nf = 0; nf < 4; nf++) {
            const int col = bn * 128 + wx * 32 + nf * 8 + tig * 2;
            #pragma unroll
            for (int half = 0; half < 2; half++) {
                const int r = row + half * 8;
                float vx = acc[mf][nf][half*2 + 0];
                float vy = acc[mf][nf][half*2 + 1];
                if (bias) { vx += bsv[nf].x; vy += bsv[nf].y; }
                if (relu) { vx = fmaxf(vx, 0.f); vy = fmaxf(vy, 0.f); }
                if (out_half) {
                    *(uint32_t*)((__half*)C + (size_t)r * N + col) = f22h(vx, vy);
                } else {
                    *(float2*)((float*)C + (size_t)r * N + col) = make_float2(vx, vy);
                }
            }
        }
    }
}

// ---------------- weight transpose (fp32 -> fp16) ----------------
__global__ void __launch_bounds__(256) transpose_h_kernel(
    const float* __restrict__ in, __half* __restrict__ out, int R, int Cc)
{
    __shared__ float t[32][33];
    int r0 = blockIdx.y * 32, c0 = blockIdx.x * 32;
    #pragma unroll
    for (int i = threadIdx.y; i < 32; i += 8)
        t[i][threadIdx.x] = in[(size_t)(r0 + i) * Cc + c0 + threadIdx.x];
    __syncthreads();
    #pragma unroll
    for (int i = threadIdx.y; i < 32; i += 8)
        out[(size_t)(c0 + i) * R + r0 + threadIdx.x] = __float2half_rn(t[threadIdx.x][i]);
}

// ---------------- fused QKV weight assembly (fp16 out) ----------------
__global__ void __launch_bounds__(256) assemble_qkvB_kernel(
    const float* __restrict__ Wqr, const float* __restrict__ Wqi,
    const float* __restrict__ Wkr, const float* __restrict__ Wki,
    const float* __restrict__ Wv,  __half* __restrict__ out, int Kfull)
{
    __shared__ float t[32][33];
    const int k0 = blockIdx.x * 32, n0 = blockIdx.y * 32;
    const int blk  = n0 >> 9;
    const int half = k0 >> 9;
    const int ks   = k0 & 511;
    const int ns   = n0 & 511;

    const float* src = Wv;
    float sign = 1.f;
    bool zero = false;
    if      (blk == 0) { if (half == 0) src = Wqr; else { src = Wqi; sign = -1.f; } }
    else if (blk == 1) { if (half == 0) src = Wqi; else   src = Wqr; }
    else if (blk == 2) { if (half == 0) src = Wkr; else { src = Wki; sign = -1.f; } }
    else if (blk == 3) { if (half == 0) src = Wki; else   src = Wkr; }
    else               { if (half == 0) src = Wv;  else   zero = true; }

    #pragma unroll
    for (int i = threadIdx.y; i < 32; i += 8)
        t[i][threadIdx.x] = zero ? 0.f : src[(size_t)(ks + i) * 512 + ns + threadIdx.x];
    __syncthreads();
    #pragma unroll
    for (int i = threadIdx.y; i < 32; i += 8)
        out[(size_t)(n0 + i) * Kfull + k0 + threadIdx.x] =
            __float2half_rn(sign * t[threadIdx.x][i]);
}

// ---------------- embedding / positional ----------------
__global__ void __launch_bounds__(128) embed_kernel(
    const int* __restrict__ tok, const float* __restrict__ emb,
    float* __restrict__ zr, __half* __restrict__ acat)
{
    int row = blockIdx.x;
    int t = tok[row];
    int c4 = threadIdx.x * 4;
    float4 v = *(const float4*)(emb + (size_t)t * D_ + c4);
    *(float4*)(zr + (size_t)row * D_ + c4) = v;
    *(uint2*)(acat + (size_t)row * 2 * D_ + c4) =
        make_uint2(f22h(v.x, v.y), f22h(v.z, v.w));
}

__global__ void __launch_bounds__(256) posimag_kernel(__half* __restrict__ acat)
{
    int s = blockIdx.x;
    int j = threadIdx.x;
    float freq = expf(-((float)j * (1.0f/256.0f)) * 9.2103403719761836f);
    float val = sinf((float)s * freq);
    uint32_t vv = f22h(val, val);
    int d = D_ + j * 2;
    *(uint32_t*)(acat + (size_t)(0 * S_ + s) * 2 * D_ + d) = vv;
    *(uint32_t*)(acat + (size_t)(1 * S_ + s) * 2 * D_ + d) = vv;
}

// ---------------- fp16 TC complex-hybrid flash attention ----------------
// 128 q-rows/CTA, 8 warps, cp.async double-buffered staging, x4 ldmatrix,
// P in registers, softmax transcendentals on the MUFU pipe.
__global__ void __launch_bounds__(256) attn_tc_kernel(
    const __half* __restrict__ QKV, __half* __restrict__ Out)
{
    extern __shared__ __half smh[];
    __half (*bKr)[AT_ST] = (__half(*)[AT_ST])smh;   // 128 rows: 2 stages x 64
    __half (*bKi)[AT_ST] = bKr + 128;
    __half (*bV )[AT_ST] = bKi + 128;

    const int q0 = blockIdx.x * 128;
    const int h  = blockIdx.y;
    const int b  = blockIdx.z;
    const int tid  = threadIdx.x;
    const int wid  = tid >> 5, lane = tid & 31;
    const int gid  = lane >> 2, tig = lane & 3;
    const int wrow = wid * 16;
    const size_t baseq = ((size_t)b * S_) * QKV_LD + (size_t)h * DK_;
    const size_t baseo = ((size_t)b * S_) * D_     + (size_t)h * DK_;

    const uint32_t kr_sh = (uint32_t)__cvta_generic_to_shared(bKr);
    const uint32_t ki_sh = (uint32_t)__cvta_generic_to_shared(bKi);
    const uint32_t v_sh  = (uint32_t)__cvta_generic_to_shared(bV);

    // ---- stage Q (qr into bKr[0..127], qi into bKi[0..127]) ----
    for (int i = tid; i < 128*8; i += 256) {
        int r = i >> 3, c8 = (i & 7) * 8;
        const __half* qrow = QKV + baseq + (size_t)(q0 + r) * QKV_LD + c8;
        *(uint4*)&bKr[r][c8] = *(const uint4*)(qrow);
        *(uint4*)&bKi[r][c8] = *(const uint4*)(qrow + 512);
    }
    __syncthreads();

    uint32_t aQr[4][4], aQi[4][4];
    {
        const uint32_t ro = ((uint32_t)(wrow + (lane & 15)) * AT_ST + ((lane >> 4) << 3)) * 2;
        #pragma unroll
        for (int k = 0; k < 4; k++) {
            ldmx4(aQr[k], kr_sh + ro + k * 32);
            ldmx4(aQi[k], ki_sh + ro + k * 32);
        }
    }
    __syncthreads();

    float o[8][4];
    #pragma unroll
    for (int n = 0; n < 8; n++)
        #pragma unroll
        for (int e = 0; e < 4; e++) o[n][e] = 0.f;
    float l0 = 0.f, l1 = 0.f;

    const uint32_t kb4_lo = ((uint32_t)(lane & 7) + ((lane >> 4) << 3)) * AT_ST
                          + ((lane >> 3) & 1) * 8;
    const uint32_t vb4_lo = (uint32_t)(lane & 15) * AT_ST + ((lane >> 4) << 3);

    // prologue: stage tile 0 into stage 0
    {
        for (int i = tid; i < 64*8; i += 256) {
            int r = i >> 3, c8 = (i & 7) * 8;
            const __half* krow = QKV + baseq + (size_t)r * QKV_LD + c8;
            cp_async16(&bKr[r][c8], krow + 1024);
            cp_async16(&bKi[r][c8], krow + 1536);
            cp_async16(&bV [r][c8], krow + 2048);
        }
        CP_COMMIT();
    }

    const int NT = S_ / 64;
    for (int ti = 0; ti < NT; ti++) {
        CP_WAIT0();
        __syncthreads();
        if (ti + 1 < NT) {
            const int sn = (ti + 1) & 1;
            const int kt = (ti + 1) * 64;
            for (int i = tid; i < 64*8; i += 256) {
                int r = i >> 3, c8 = (i & 7) * 8;
                const __half* krow = QKV + baseq + (size_t)(kt + r) * QKV_LD + c8;
                cp_async16(&bKr[sn*64 + r][c8], krow + 1024);
                cp_async16(&bKi[sn*64 + r][c8], krow + 1536);
                cp_async16(&bV [sn*64 + r][c8], krow + 2048);
            }
            CP_COMMIT();
        }
        const int s = ti & 1;
        const uint32_t soff = (uint32_t)(s * 64) * AT_ST * 2;

        // ---- scores ----
        float srf[8][4], sif[8][4];
        #pragma unroll
        for (int n = 0; n < 8; n++)
            #pragma unroll
            for (int e = 0; e < 4; e++) { srf[n][e] = 0.f; sif[n][e] = 0.f; }

        #pragma unroll
        for (int k = 0; k < 4; k++) {
            #pragma unroll
            for (int p = 0; p < 4; p++) {
                const uint32_t off = soff + ((uint32_t)(p * 16) * AT_ST + k * 16 + kb4_lo) * 2;
                uint32_t br[4], bi[4];
                ldmx4(br, kr_sh + off);
                ldmx4(bi, ki_sh + off);
                MMA_F16(srf[2*p    ], aQr[k], br[0], br[1]);
                MMA_F16(srf[2*p    ], aQi[k], bi[0], bi[1]);
                MMA_F16(sif[2*p    ], aQi[k], br[0], br[1]);
                uint32_t x0 = bi[0] ^ 0x80008000u, x1 = bi[1] ^ 0x80008000u;
                MMA_F16(sif[2*p    ], aQr[k], x0, x1);
                MMA_F16(srf[2*p + 1], aQr[k], br[2], br[3]);
                MMA_F16(srf[2*p + 1], aQi[k], bi[2], bi[3]);
                MMA_F16(sif[2*p + 1], aQi[k], br[2], br[3]);
                uint32_t x2 = bi[2] ^ 0x80008000u, x3 = bi[3] ^ 0x80008000u;
                MMA_F16(sif[2*p + 1], aQr[k], x2, x3);
            }
        }

        // ---- hybrid score -> p (MUFU rsqrt + exp; FMA pipe kept light) ----
        float psum0 = 0.f, psum1 = 0.f;
        #pragma unroll
        for (int n = 0; n < 8; n++) {
            #pragma unroll
            for (int e = 0; e < 4; e++) {
                float a = srf[n][e], c = sif[n][e];
                float m2 = fmaf(a, a, c * c);
                float y  = rsqrtf(m2);                 // MUFU.RSQ
                float sc = y * fmaf(0.015625f, m2, 0.0375f * a);
                sc = (m2 == 0.f) ? 0.0375f : sc;
                float p = __expf(sc);                  // MUFU.EX2 path
                srf[n][e] = p;
                if (e < 2) psum0 += p; else psum1 += p;
            }
        }
        psum0 += __shfl_xor_sync(0xffffffffu, psum0, 1);
        psum0 += __shfl_xor_sync(0xffffffffu, psum0, 2);
        psum1 += __shfl_xor_sync(0xffffffffu, psum1, 1);
        psum1 += __shfl_xor_sync(0xffffffffu, psum1, 2);
        l0 += psum0; l1 += psum1;

        // ---- PV: P in registers; V fragments via ldmatrix.x4.trans ----
        #pragma unroll
        for (int kc = 0; kc < 4; kc++) {
            uint32_t ap[4];
            ap[0] = f22h(srf[2*kc  ][0], srf[2*kc  ][1]);
            ap[1] = f22h(srf[2*kc  ][2], srf[2*kc  ][3]);
            ap[2] = f22h(srf[2*kc+1][0], srf[2*kc+1][1]);
            ap[3] = f22h(srf[2*kc+1][2], srf[2*kc+1][3]);
            #pragma unroll
            for (int p = 0; p < 4; p++) {
                const uint32_t off = soff + ((uint32_t)(kc * 16) * AT_ST + p * 16 + vb4_lo) * 2;
                uint32_t bv[4];
                ldmx4t(bv, v_sh + off);
                MMA_F16(o[2*p    ], ap, bv[0], bv[1]);
                MMA_F16(o[2*p + 1], ap, bv[2], bv[3]);
            }
        }
    }

    const float inv0 = 1.0f / l0;
    const float inv1 = 1.0f / l1;
    #pragma unroll
    for (int n = 0; n < 8; n++) {
        const int col = n * 8 + 2 * tig;
        *(uint32_t*)(Out + baseo + (size_t)(q0 + wrow + gid    ) * D_ + col) =
            f22h(o[n][0] * inv0, o[n][1] * inv0);
        *(uint32_t*)(Out + baseo + (size_t)(q0 + wrow + gid + 8) * D_ + col) =
            f22h(o[n][2] * inv1, o[n][3] * inv1);
    }
}

// ---------------- fused residual + layernorm ----------------
__global__ void __launch_bounds__(128) ln_res_kernel(
    const float* __restrict__ x, const float* __restrict__ r,
    const float* __restrict__ g, const float* __restrict__ be,
    float* __restrict__ outf, __half* __restrict__ outh)
{
    __shared__ float red[8];
    int row = blockIdx.x, tid = threadIdx.x;
    float4 xv = *(const float4*)(x + (size_t)row * D_ + tid * 4);
    float4 rv = *(const float4*)(r + (size_t)row * D_ + tid * 4);
    float v0 = xv.x + rv.x, v1 = xv.y + rv.y, v2 = xv.z + rv.z, v3 = xv.w + rv.w;
    float s  = v0 + v1 + v2 + v3;
    float s2 = v0*v0 + v1*v1 + v2*v2 + v3*v3;
    #pragma unroll
    for (int o = 16; o >= 1; o >>= 1) {
        s  += __shfl_xor_sync(0xffffffffu, s,  o);
        s2 += __shfl_xor_sync(0xffffffffu, s2, o);
    }
    int warp = tid >> 5, lane = tid & 31;
    if (lane == 0) { red[warp] = s; red[4 + warp] = s2; }
    __syncthreads();
    s  = red[0] + red[1] + red[2] + red[3];
    s2 = red[4] + red[5] + red[6] + red[7];
    float mu  = s  * (1.0f / D_);
    float var = s2 * (1.0f / D_) - mu * mu;
    float inv = rsqrtf(var + 1e-5f);
    float4 gv = *(const float4*)(g  + tid * 4);
    float4 bv = *(const float4*)(be + tid * 4);
    float4 o4;
    o4.x = (v0 - mu) * inv * gv.x + bv.x;
    o4.y = (v1 - mu) * inv * gv.y + bv.y;
    o4.z = (v2 - mu) * inv * gv.z + bv.z;
    o4.w = (v3 - mu) * inv * gv.w + bv.w;
    *(float4*)(outf + (size_t)row * D_ + tid * 4) = o4;
    *(uint2*)(outh + (size_t)row * D_ + tid * 4) =
        make_uint2(f22h(o4.x, o4.y), f22h(o4.z, o4.w));
}

// ---------------- classification head ----------------
__global__ void __launch_bounds__(256) head_kernel(
    const float* __restrict__ z, const float* __restrict__ w,
    const float* __restrict__ hb, float* __restrict__ out)
{
    int warp = threadIdx.x >> 5, lane = threadIdx.x & 31;
    int row = blockIdx.x * 8 + warp;
    const float* zr = z + (size_t)row * D_;
    float s0 = 0.f, s1 = 0.f;
    for (int d = lane; d < D_; d += 32) {
        float zv = zr[d];
        s0 += zv * w[d*2 + 0];
        s1 += zv * w[d*2 + 1];
    }
    #pragma unroll
    for (int o = 16; o >= 1; o >>= 1) {
        s0 += __shfl_xor_sync(0xffffffffu, s0, o);
        s1 += __shfl_xor_sync(0xffffffffu, s1, o);
    }
    if (lane == 0) {
        out[row*2 + 0] = s0 + hb[0];
        out[row*2 + 1] = s1 + hb[1];
    }
}

// ---------------- host-side orchestration ----------------
static inline void launch_gemm(const __half* A, const __half* Bt, void* C,
                               int M, int N, int K, const float* bias, int relu,
                               int out_half)
{
    dim3 grid(N / 128, M / 128);
    tc_gemm_h_kernel<<<grid, 256>>>(A, Bt, C, M, N, K, bias, relu, out_half);
}

static inline void launch_transpose(const float* in, __half* out, int R, int Cc)
{
    dim3 grid(Cc / 32, R / 32);
    transpose_h_kernel<<<grid, dim3(32, 8)>>>(in, out, R, Cc);
}

extern "C" void kernel_launch(void* const* d_in, const int* in_sizes, int n_in,
                              void* d_out, int out_size)
{
    (void)in_sizes; (void)n_in; (void)out_size;
    const int*   tokens = (const int*)  d_in[0];
    const float* embed  = (const float*)d_in[1];
    const float* Wqr = (const float*)d_in[2];
    const float* Wqi = (const float*)d_in[3];
    const float* Wkr = (const float*)d_in[4];
    const float* Wki = (const float*)d_in[5];
    const float* Wv  = (const float*)d_in[6];
    const float* Wo  = (const float*)d_in[7];
    const float* bo  = (const float*)d_in[8];
    const float* W1  = (const float*)d_in[9];
    const float* b1  = (const float*)d_in[10];
    const float* W2  = (const float*)d_in[11];
    const float* b2  = (const float*)d_in[12];
    const float* g1  = (const float*)d_in[13];
    const float* be1 = (const float*)d_in[14];
    const float* g2  = (const float*)d_in[15];
    const float* be2 = (const float*)d_in[16];
    const float* hw  = (const float*)d_in[17];
    const float* hb  = (const float*)d_in[18];
    float* out = (float*)d_out;

    float *zr,*t0,*z1;
    __half *zrh,*acat,*qkvh,*ctxh,*z1h,*ffh,*b0h,*b1h,*wth;
    cudaGetSymbolAddress((void**)&zr,   g_zr);
    cudaGetSymbolAddress((void**)&zrh,  g_zrh);
    cudaGetSymbolAddress((void**)&acat, g_acat);
    cudaGetSymbolAddress((void**)&qkvh, g_qkvh);
    cudaGetSymbolAddress((void**)&ctxh, g_ctxh);
    cudaGetSymbolAddress((void**)&t0,   g_t0);
    cudaGetSymbolAddress((void**)&z1,   g_z1);
    cudaGetSymbolAddress((void**)&z1h,  g_z1h);
    cudaGetSymbolAddress((void**)&ffh,  g_ffh);
    cudaGetSymbolAddress((void**)&b0h,  g_b0h);
    cudaGetSymbolAddress((void**)&b1h,  g_b1h);
    cudaGetSymbolAddress((void**)&wth,  g_wth);

    cudaFuncSetAttribute(attn_tc_kernel, cudaFuncAttributeMaxDynamicSharedMemorySize,
                         ATTN_SMEM_BYTES);

    embed_kernel<<<ROWS, 128>>>(tokens, embed, zr, acat);
    posimag_kernel<<<S_, 256>>>(acat);

    const size_t DD = (size_t)D_ * D_;
    const size_t DF = (size_t)D_ * DFF_;

    {
        dim3 g0(2 * D_ / 32, QKV_N / 32);
        assemble_qkvB_kernel<<<g0, dim3(32, 8)>>>(Wqr, Wqi, Wkr, Wki, Wv, b0h, 2 * D_);
        dim3 g1d(D_ / 32, QKV_N / 32);
        assemble_qkvB_kernel<<<g1d, dim3(32, 8)>>>(Wqr + DD, Wqi + DD, Wkr + DD,
                                                   Wki + DD, Wv + DD, b1h, D_);
    }
    for (int l = 0; l < L_; l++) {
        __half* base = wth + (size_t)l * WT2_PER_LAYER;
        launch_transpose(Wo + l*DD, base,           D_,   D_);
        launch_transpose(W1 + l*DF, base + DD,      D_,   DFF_);
        launch_transpose(W2 + l*DF, base + DD + DF, DFF_, D_);
    }

    for (int l = 0; l < L_; l++) {
        __half* base = wth + (size_t)l * WT2_PER_LAYER;
        const __half* woT  = base;
        const __half* w1T  = base + DD;
        const __half* w2T  = base + DD + DF;
        const float* bo_l  = bo  + (size_t)l * D_;
        const float* b1_l  = b1  + (size_t)l * DFF_;
        const float* b2_l  = b2  + (size_t)l * D_;
        const float* g1_l  = g1  + (size_t)l * D_;
        const float* be1_l = be1 + (size_t)l * D_;
        const float* g2_l  = g2  + (size_t)l * D_;
        const float* be2_l = be2 + (size_t)l * D_;

        if (l == 0)
            launch_gemm(acat, b0h, qkvh, ROWS, QKV_N, 2 * D_, nullptr, 0, 1);
        else
            launch_gemm(zrh, b1h, qkvh, ROWS, QKV_N, D_, nullptr, 0, 1);

        dim3 ag(S_ / 128, H_, B_);
        attn_tc_kernel<<<ag, 256, ATTN_SMEM_BYTES>>>(qkvh, ctxh);

        launch_gemm(ctxh, woT, t0, ROWS, D_, D_, bo_l, 0, 0);
        ln_res_kernel<<<ROWS, 128>>>(zr, t0, g1_l, be1_l, z1, z1h);
        launch_gemm(z1h, w1T, ffh, ROWS, DFF_, D_, b1_l, 1, 1);
        launch_gemm(ffh, w2T, t0, ROWS, D_, DFF_, b2_l, 0, 0);
        ln_res_kernel<<<ROWS, 128>>>(z1, t0, g2_l, be2_l, zr, zrh);
    }

    head_kernel<<<ROWS / 8, 256>>>(zr, hw, hb, out);
}

// round 14
// speedup vs baseline: 1.1396x; 1.0748x over previous
#include <cuda_runtime.h>
#include <cuda_fp16.h>
#include <math.h>
#include <stdint.h>

#define B_   2
#define S_   2048
#define D_   512
#define H_   8
#define DK_  64
#define DFF_ 2048
#define L_   2
#define ROWS (B_*S_)   /* 4096 */

#define QKV_N  2560
#define QKV_LD 2560
#define AT_ST 72
#define ATTN_SMEM_BYTES (6 * 64 * AT_ST * 2)   /* 55296 */

/* 3-stage GEMM smem: per stage As(128x40)+Bs(128x40) halves */
#define GST      (128*40)            /* halves per matrix per stage */
#define GSTAGE   (2*GST)             /* halves per stage */
#define GEMM_SMEM_BYTES (3 * GSTAGE * 2)   /* 61440 */

// ---------------- scratch ----------------
__device__ float  g_zr  [ROWS * D_];
__device__ __half g_zrh [ROWS * D_];
__device__ __half g_acat[ROWS * 2 * D_];
__device__ __half g_qkvh[ROWS * QKV_LD];
__device__ __half g_ctxh[ROWS * D_];
__device__ float  g_t0  [ROWS * D_];
__device__ float  g_z1  [ROWS * D_];
__device__ __half g_z1h [ROWS * D_];
__device__ __half g_ffh [ROWS * DFF_];
__device__ __half g_b0h [QKV_N * 2 * D_];
__device__ __half g_b1h [QKV_N * D_];
#define WT2_PER_LAYER (D_*D_ + 2*D_*DFF_)
__device__ __half g_wth [L_ * WT2_PER_LAYER];

__device__ __forceinline__ uint32_t f22h(float a, float b) {
    __half2 h = __floats2half2_rn(a, b);
    return *(uint32_t*)&h;
}

#define MMA_F16(acc, a, b0, b1) \
    asm volatile("mma.sync.aligned.m16n8k16.row.col.f32.f16.f16.f32 " \
        "{%0,%1,%2,%3}, {%4,%5,%6,%7}, {%8,%9}, {%0,%1,%2,%3};" \
        : "+f"((acc)[0]), "+f"((acc)[1]), "+f"((acc)[2]), "+f"((acc)[3]) \
        : "r"((a)[0]), "r"((a)[1]), "r"((a)[2]), "r"((a)[3]), "r"(b0), "r"(b1))

__device__ __forceinline__ void cp_async16(void* smem, const void* gmem) {
    uint32_t s = (uint32_t)__cvta_generic_to_shared(smem);
    asm volatile("cp.async.cg.shared.global [%0], [%1], 16;" :: "r"(s), "l"(gmem));
}
#define CP_COMMIT() asm volatile("cp.async.commit_group;" ::: "memory")
#define CP_WAIT0()  asm volatile("cp.async.wait_group 0;"  ::: "memory")
#define CP_WAIT1()  asm volatile("cp.async.wait_group 1;"  ::: "memory")

__device__ __forceinline__ void ldmx4(uint32_t* r, uint32_t addr) {
    asm volatile("ldmatrix.sync.aligned.m8n8.x4.shared.b16 {%0,%1,%2,%3}, [%4];"
        : "=r"(r[0]), "=r"(r[1]), "=r"(r[2]), "=r"(r[3]) : "r"(addr));
}
__device__ __forceinline__ void ldmx4t(uint32_t* r, uint32_t addr) {
    asm volatile("ldmatrix.sync.aligned.m8n8.x4.trans.shared.b16 {%0,%1,%2,%3}, [%4];"
        : "=r"(r[0]), "=r"(r[1]), "=r"(r[2]), "=r"(r[3]) : "r"(addr));
}

// ---------------- all-fp16 3-stage pipelined tensor-core GEMM ----------------
__global__ void __launch_bounds__(256) tc_gemm_h_kernel(
    const __half* __restrict__ A, const __half* __restrict__ Bt, void* __restrict__ C,
    int M, int N, int K, const float* __restrict__ bias, int relu, int out_half)
{
    extern __shared__ __half gsm[];

    const int tid  = threadIdx.x;
    const int wid  = tid >> 5, lane = tid & 31;
    const int gid  = lane >> 2, tig = lane & 3;
    const int wy   = wid >> 2, wx = wid & 3;
    const int bm   = blockIdx.y, bn = blockIdx.x;

    const __half* Ab = A  + (size_t)bm * 128 * K;
    const __half* Bb = Bt + (size_t)bn * 128 * K;

    const int lr = tid >> 2;
    const int c8 = (tid & 3) * 8;

    const uint32_t sm_sh = (uint32_t)__cvta_generic_to_shared(gsm);
    const uint32_t a_lo  = (uint32_t)(lane & 15) * 40 + ((lane >> 4) << 3);
    const uint32_t b4_lo = ((uint32_t)(lane & 7) + ((lane >> 4) << 3)) * 40 + ((lane >> 3) & 1) * 8;

    float acc[4][4][4];
    #pragma unroll
    for (int i = 0; i < 4; i++)
        #pragma unroll
        for (int j = 0; j < 4; j++)
            #pragma unroll
            for (int r = 0; r < 4; r++) acc[i][j][r] = 0.f;

    const int nch = K >> 5;

    // prologue: load chunks 0,1 into stages 0,1
    #pragma unroll
    for (int pc = 0; pc < 2; pc++) {
        if (pc < nch) {
            __half* As = gsm + pc * GSTAGE;
            __half* Bs = As + GST;
            const __half* a0 = Ab + (size_t)lr * K + pc * 32 + c8;
            const __half* b0 = Bb + (size_t)lr * K + pc * 32 + c8;
            cp_async16(&As[(size_t)lr * 40 + c8],        a0);
            cp_async16(&As[(size_t)(lr + 64) * 40 + c8], a0 + (size_t)64 * K);
            cp_async16(&Bs[(size_t)lr * 40 + c8],        b0);
            cp_async16(&Bs[(size_t)(lr + 64) * 40 + c8], b0 + (size_t)64 * K);
        }
        CP_COMMIT();
    }

    for (int c = 0; c < nch; c++) {
        CP_WAIT1();
        __syncthreads();
        {
            // always commit (possibly empty) to keep group accounting uniform
            if (c + 2 < nch) {
                const int sn = (c + 2) % 3;
                __half* As = gsm + sn * GSTAGE;
                __half* Bs = As + GST;
                const int kg = (c + 2) * 32 + c8;
                const __half* a0 = Ab + (size_t)lr * K + kg;
                const __half* b0 = Bb + (size_t)lr * K + kg;
                cp_async16(&As[(size_t)lr * 40 + c8],        a0);
                cp_async16(&As[(size_t)(lr + 64) * 40 + c8], a0 + (size_t)64 * K);
                cp_async16(&Bs[(size_t)lr * 40 + c8],        b0);
                cp_async16(&Bs[(size_t)(lr + 64) * 40 + c8], b0 + (size_t)64 * K);
            }
            CP_COMMIT();
        }
        const int s = c % 3;
        const uint32_t abase = sm_sh + (uint32_t)s * GSTAGE * 2;
        const uint32_t bbase = abase + GST * 2;
        #pragma unroll
        for (int ks = 0; ks < 2; ks++) {
            uint32_t af[4][4];
            #pragma unroll
            for (int mf = 0; mf < 4; mf++)
                ldmx4(af[mf], abase + ((uint32_t)(wy*64 + mf*16) * 40 + ks*16 + a_lo) * 2);
            uint32_t bf[2][4];
            #pragma unroll
            for (int p = 0; p < 2; p++)
                ldmx4(bf[p], bbase + ((uint32_t)(wx*32 + p*16) * 40 + ks*16 + b4_lo) * 2);
            #pragma unroll
            for (int mf = 0; mf < 4; mf++)
                #pragma unroll
                for (int p = 0; p < 2; p++) {
                    MMA_F16(acc[mf][2*p    ], af[mf], bf[p][0], bf[p][1]);
                    MMA_F16(acc[mf][2*p + 1], af[mf], bf[p][2], bf[p][3]);
                }
        }
    }

    float2 bsv[4];
    if (bias) {
        #pragma unroll
        for (int nf = 0; nf < 4; nf++) {
            const int col = bn * 128 + wx * 32 + nf * 8 + tig * 2;
            bsv[nf] = *(const float2*)(bias + col);
        }
    }
    #pragma unroll
    for (int mf = 0; mf < 4; mf++) {
        const int row = bm * 128 + wy * 64 + mf * 16 + gid;
        #pragma unroll
        for (int nf = 0; nf < 4; nf++) {
            const int col = bn * 128 + wx * 32 + nf * 8 + tig * 2;
            #pragma unroll
            for (int half = 0; half < 2; half++) {
                const int r = row + half * 8;
                float vx = acc[mf][nf][half*2 + 0];
                float vy = acc[mf][nf][half*2 + 1];
                if (bias) { vx += bsv[nf].x; vy += bsv[nf].y; }
                if (relu) { vx = fmaxf(vx, 0.f); vy = fmaxf(vy, 0.f); }
                if (out_half) {
                    *(uint32_t*)((__half*)C + (size_t)r * N + col) = f22h(vx, vy);
                } else {
                    *(float2*)((float*)C + (size_t)r * N + col) = make_float2(vx, vy);
                }
            }
        }
    }
}

// ---------------- batched weight prep: assembles + transposes in ONE launch ----
// Tile jobs (32x32 tiles, 32x8 threads):
//   [0, 2560)      assemble b0 (Kfull=1024, layer-0 weights)
//   [2560, 3840)   assemble b1 (Kfull=512,  layer-1 weights)
//   then per layer: Wo (512x512,256 tiles), W1 (512x2048,1024), W2 (2048x512,1024)
#define PREP_A0   2560
#define PREP_A1   (PREP_A0 + 1280)
#define PREP_TPL  (256 + 1024 + 1024)
#define PREP_TOTAL (PREP_A1 + 2 * PREP_TPL)

__device__ __forceinline__ void prep_assemble(
    const float* Wqr, const float* Wqi, const float* Wkr, const float* Wki,
    const float* Wv, __half* out, int Kfull, int t, float sm[32][33])
{
    const int ntk = Kfull >> 5;
    const int k0 = (t % ntk) * 32, n0 = (t / ntk) * 32;
    const int blk  = n0 >> 9;
    const int half = k0 >> 9;
    const int ks   = k0 & 511;
    const int ns   = n0 & 511;

    const float* src = Wv;
    float sign = 1.f;
    bool zero = false;
    if      (blk == 0) { if (half == 0) src = Wqr; else { src = Wqi; sign = -1.f; } }
    else if (blk == 1) { if (half == 0) src = Wqi; else   src = Wqr; }
    else if (blk == 2) { if (half == 0) src = Wkr; else { src = Wki; sign = -1.f; } }
    else if (blk == 3) { if (half == 0) src = Wki; else   src = Wkr; }
    else               { if (half == 0) src = Wv;  else   zero = true; }

    #pragma unroll
    for (int i = threadIdx.y; i < 32; i += 8)
        sm[i][threadIdx.x] = zero ? 0.f : src[(size_t)(ks + i) * 512 + ns + threadIdx.x];
    __syncthreads();
    #pragma unroll
    for (int i = threadIdx.y; i < 32; i += 8)
        out[(size_t)(n0 + i) * Kfull + k0 + threadIdx.x] =
            __float2half_rn(sign * sm[threadIdx.x][i]);
}

__device__ __forceinline__ void prep_transpose(
    const float* in, __half* out, int R, int Cc, int t, float sm[32][33])
{
    const int ntc = Cc >> 5;
    const int c0 = (t % ntc) * 32, r0 = (t / ntc) * 32;
    #pragma unroll
    for (int i = threadIdx.y; i < 32; i += 8)
        sm[i][threadIdx.x] = in[(size_t)(r0 + i) * Cc + c0 + threadIdx.x];
    __syncthreads();
    #pragma unroll
    for (int i = threadIdx.y; i < 32; i += 8)
        out[(size_t)(c0 + i) * R + r0 + threadIdx.x] = __float2half_rn(sm[threadIdx.x][i]);
}

__global__ void __launch_bounds__(256) prep_weights_kernel(
    const float* __restrict__ Wqr, const float* __restrict__ Wqi,
    const float* __restrict__ Wkr, const float* __restrict__ Wki,
    const float* __restrict__ Wv,  const float* __restrict__ Wo,
    const float* __restrict__ W1,  const float* __restrict__ W2,
    __half* __restrict__ b0h, __half* __restrict__ b1h, __half* __restrict__ wth)
{
    __shared__ float sm[32][33];
    const size_t DD = (size_t)D_ * D_;
    const size_t DF = (size_t)D_ * DFF_;
    int bid = blockIdx.x;

    if (bid < PREP_A0) {
        prep_assemble(Wqr, Wqi, Wkr, Wki, Wv, b0h, 2 * D_, bid, sm);
        return;
    }
    bid -= PREP_A0;
    if (bid < 1280) {
        prep_assemble(Wqr + DD, Wqi + DD, Wkr + DD, Wki + DD, Wv + DD, b1h, D_, bid, sm);
        return;
    }
    bid -= 1280;
    const int l = bid / PREP_TPL;
    int t = bid % PREP_TPL;
    __half* base = wth + (size_t)l * WT2_PER_LAYER;
    if (t < 256)        { prep_transpose(Wo + l*DD, base,           D_,   D_,   t,        sm); }
    else if (t < 1280)  { prep_transpose(W1 + l*DF, base + DD,      D_,   DFF_, t - 256,  sm); }
    else                { prep_transpose(W2 + l*DF, base + DD + DF, DFF_, D_,   t - 1280, sm); }
}

// ---------------- fused embedding + positional imag ----------------
__global__ void __launch_bounds__(256) embed_pos_kernel(
    const int* __restrict__ tok, const float* __restrict__ emb,
    float* __restrict__ zr, __half* __restrict__ acat)
{
    int row = blockIdx.x;
    int tid = threadIdx.x;
    if (tid < 128) {
        int t = tok[row];
        int c4 = tid * 4;
        float4 v = *(const float4*)(emb + (size_t)t * D_ + c4);
        *(float4*)(zr + (size_t)row * D_ + c4) = v;
        *(uint2*)(acat + (size_t)row * 2 * D_ + c4) =
            make_uint2(f22h(v.x, v.y), f22h(v.z, v.w));
    } else {
        int s = row & (S_ - 1);
        int j2 = (tid - 128) * 2;        // j2, j2+1
        float f0 = __expf(-((float)(j2    ) * (1.0f/256.0f)) * 9.2103403719761836f);
        float f1 = __expf(-((float)(j2 + 1) * (1.0f/256.0f)) * 9.2103403719761836f);
        float v0 = sinf((float)s * f0);
        float v1 = sinf((float)s * f1);
        *(uint2*)(acat + (size_t)row * 2 * D_ + D_ + j2 * 2) =
            make_uint2(f22h(v0, v0), f22h(v1, v1));
    }
}

// ---------------- fp16 TC complex-hybrid flash attention (R12 winner) ----------
__global__ void __launch_bounds__(256) attn_tc_kernel(
    const __half* __restrict__ QKV, __half* __restrict__ Out)
{
    extern __shared__ __half smh[];
    __half (*bKr)[AT_ST] = (__half(*)[AT_ST])smh;
    __half (*bKi)[AT_ST] = bKr + 128;
    __half (*bV )[AT_ST] = bKi + 128;

    const int q0 = blockIdx.x * 128;
    const int h  = blockIdx.y;
    const int b  = blockIdx.z;
    const int tid  = threadIdx.x;
    const int wid  = tid >> 5, lane = tid & 31;
    const int gid  = lane >> 2, tig = lane & 3;
    const int wrow = wid * 16;
    const size_t baseq = ((size_t)b * S_) * QKV_LD + (size_t)h * DK_;
    const size_t baseo = ((size_t)b * S_) * D_     + (size_t)h * DK_;

    const uint32_t kr_sh = (uint32_t)__cvta_generic_to_shared(bKr);
    const uint32_t ki_sh = (uint32_t)__cvta_generic_to_shared(bKi);
    const uint32_t v_sh  = (uint32_t)__cvta_generic_to_shared(bV);

    for (int i = tid; i < 128*8; i += 256) {
        int r = i >> 3, c8 = (i & 7) * 8;
        const __half* qrow = QKV + baseq + (size_t)(q0 + r) * QKV_LD + c8;
        *(uint4*)&bKr[r][c8] = *(const uint4*)(qrow);
        *(uint4*)&bKi[r][c8] = *(const uint4*)(qrow + 512);
    }
    __syncthreads();

    uint32_t aQr[4][4], aQi[4][4];
    {
        const uint32_t ro = ((uint32_t)(wrow + (lane & 15)) * AT_ST + ((lane >> 4) << 3)) * 2;
        #pragma unroll
        for (int k = 0; k < 4; k++) {
            ldmx4(aQr[k], kr_sh + ro + k * 32);
            ldmx4(aQi[k], ki_sh + ro + k * 32);
        }
    }
    __syncthreads();

    float o[8][4];
    #pragma unroll
    for (int n = 0; n < 8; n++)
        #pragma unroll
        for (int e = 0; e < 4; e++) o[n][e] = 0.f;
    float l0 = 0.f, l1 = 0.f;

    const uint32_t kb4_lo = ((uint32_t)(lane & 7) + ((lane >> 4) << 3)) * AT_ST
                          + ((lane >> 3) & 1) * 8;
    const uint32_t vb4_lo = (uint32_t)(lane & 15) * AT_ST + ((lane >> 4) << 3);

    {
        for (int i = tid; i < 64*8; i += 256) {
            int r = i >> 3, c8 = (i & 7) * 8;
            const __half* krow = QKV + baseq + (size_t)r * QKV_LD + c8;
            cp_async16(&bKr[r][c8], krow + 1024);
            cp_async16(&bKi[r][c8], krow + 1536);
            cp_async16(&bV [r][c8], krow + 2048);
        }
        CP_COMMIT();
    }

    const int NT = S_ / 64;
    for (int ti = 0; ti < NT; ti++) {
        CP_WAIT0();
        __syncthreads();
        if (ti + 1 < NT) {
            const int sn = (ti + 1) & 1;
            const int kt = (ti + 1) * 64;
            for (int i = tid; i < 64*8; i += 256) {
                int r = i >> 3, c8 = (i & 7) * 8;
                const __half* krow = QKV + baseq + (size_t)(kt + r) * QKV_LD + c8;
                cp_async16(&bKr[sn*64 + r][c8], krow + 1024);
                cp_async16(&bKi[sn*64 + r][c8], krow + 1536);
                cp_async16(&bV [sn*64 + r][c8], krow + 2048);
            }
            CP_COMMIT();
        }
        const int s = ti & 1;
        const uint32_t soff = (uint32_t)(s * 64) * AT_ST * 2;

        float srf[8][4], sif[8][4];
        #pragma unroll
        for (int n = 0; n < 8; n++)
            #pragma unroll
            for (int e = 0; e < 4; e++) { srf[n][e] = 0.f; sif[n][e] = 0.f; }

        #pragma unroll
        for (int k = 0; k < 4; k++) {
            #pragma unroll
            for (int p = 0; p < 4; p++) {
                const uint32_t off = soff + ((uint32_t)(p * 16) * AT_ST + k * 16 + kb4_lo) * 2;
                uint32_t br[4], bi[4];
                ldmx4(br, kr_sh + off);
                ldmx4(bi, ki_sh + off);
                MMA_F16(srf[2*p    ], aQr[k], br[0], br[1]);
                MMA_F16(srf[2*p    ], aQi[k], bi[0], bi[1]);
                MMA_F16(sif[2*p    ], aQi[k], br[0], br[1]);
                uint32_t x0 = bi[0] ^ 0x80008000u, x1 = bi[1] ^ 0x80008000u;
                MMA_F16(sif[2*p    ], aQr[k], x0, x1);
                MMA_F16(srf[2*p + 1], aQr[k], br[2], br[3]);
                MMA_F16(srf[2*p + 1], aQi[k], bi[2], bi[3]);
                MMA_F16(sif[2*p + 1], aQi[k], br[2], br[3]);
                uint32_t x2 = bi[2] ^ 0x80008000u, x3 = bi[3] ^ 0x80008000u;
                MMA_F16(sif[2*p + 1], aQr[k], x2, x3);
            }
        }

        float psum0 = 0.f, psum1 = 0.f;
        #pragma unroll
        for (int n = 0; n < 8; n++) {
            #pragma unroll
            for (int e = 0; e < 4; e++) {
                float a = srf[n][e], c = sif[n][e];
                float m2 = fmaf(a, a, c * c);
                float y  = rsqrtf(m2);
                float sc = y * fmaf(0.015625f, m2, 0.0375f * a);
                sc = (m2 == 0.f) ? 0.0375f : sc;
                float p = __expf(sc);
                srf[n][e] = p;
                if (e < 2) psum0 += p; else psum1 += p;
            }
        }
        psum0 += __shfl_xor_sync(0xffffffffu, psum0, 1);
        psum0 += __shfl_xor_sync(0xffffffffu, psum0, 2);
        psum1 += __shfl_xor_sync(0xffffffffu, psum1, 1);
        psum1 += __shfl_xor_sync(0xffffffffu, psum1, 2);
        l0 += psum0; l1 += psum1;

        #pragma unroll
        for (int kc = 0; kc < 4; kc++) {
            uint32_t ap[4];
            ap[0] = f22h(srf[2*kc  ][0], srf[2*kc  ][1]);
            ap[1] = f22h(srf[2*kc  ][2], srf[2*kc  ][3]);
            ap[2] = f22h(srf[2*kc+1][0], srf[2*kc+1][1]);
            ap[3] = f22h(srf[2*kc+1][2], srf[2*kc+1][3]);
            #pragma unroll
            for (int p = 0; p < 4; p++) {
                const uint32_t off = soff + ((uint32_t)(kc * 16) * AT_ST + p * 16 + vb4_lo) * 2;
                uint32_t bv[4];
                ldmx4t(bv, v_sh + off);
                MMA_F16(o[2*p    ], ap, bv[0], bv[1]);
                MMA_F16(o[2*p + 1], ap, bv[2], bv[3]);
            }
        }
    }

    const float inv0 = 1.0f / l0;
    const float inv1 = 1.0f / l1;
    #pragma unroll
    for (int n = 0; n < 8; n++) {
        const int col = n * 8 + 2 * tig;
        *(uint32_t*)(Out + baseo + (size_t)(q0 + wrow + gid    ) * D_ + col) =
            f22h(o[n][0] * inv0, o[n][1] * inv0);
        *(uint32_t*)(Out + baseo + (size_t)(q0 + wrow + gid + 8) * D_ + col) =
            f22h(o[n][2] * inv1, o[n][3] * inv1);
    }
}

// ---------------- fused residual + layernorm ----------------
__global__ void __launch_bounds__(128) ln_res_kernel(
    const float* __restrict__ x, const float* __restrict__ r,
    const float* __restrict__ g, const float* __restrict__ be,
    float* __restrict__ outf, __half* __restrict__ outh)
{
    __shared__ float red[8];
    int row = blockIdx.x, tid = threadIdx.x;
    float4 xv = *(const float4*)(x + (size_t)row * D_ + tid * 4);
    float4 rv = *(const float4*)(r + (size_t)row * D_ + tid * 4);
    float v0 = xv.x + rv.x, v1 = xv.y + rv.y, v2 = xv.z + rv.z, v3 = xv.w + rv.w;
    float s  = v0 + v1 + v2 + v3;
    float s2 = v0*v0 + v1*v1 + v2*v2 + v3*v3;
    #pragma unroll
    for (int o = 16; o >= 1; o >>= 1) {
        s  += __shfl_xor_sync(0xffffffffu, s,  o);
        s2 += __shfl_xor_sync(0xffffffffu, s2, o);
    }
    int warp = tid >> 5, lane = tid & 31;
    if (lane == 0) { red[warp] = s; red[4 + warp] = s2; }
    __syncthreads();
    s  = red[0] + red[1] + red[2] + red[3];
    s2 = red[4] + red[5] + red[6] + red[7];
    float mu  = s  * (1.0f / D_);
    float var = s2 * (1.0f / D_) - mu * mu;
    float inv = rsqrtf(var + 1e-5f);
    float4 gv = *(const float4*)(g  + tid * 4);
    float4 bv = *(const float4*)(be + tid * 4);
    float4 o4;
    o4.x = (v0 - mu) * inv * gv.x + bv.x;
    o4.y = (v1 - mu) * inv * gv.y + bv.y;
    o4.z = (v2 - mu) * inv * gv.z + bv.z;
    o4.w = (v3 - mu) * inv * gv.w + bv.w;
    *(float4*)(outf + (size_t)row * D_ + tid * 4) = o4;
    *(uint2*)(outh + (size_t)row * D_ + tid * 4) =
        make_uint2(f22h(o4.x, o4.y), f22h(o4.z, o4.w));
}

// ---------------- classification head ----------------
__global__ void __launch_bounds__(256) head_kernel(
    const float* __restrict__ z, const float* __restrict__ w,
    const float* __restrict__ hb, float* __restrict__ out)
{
    int warp = threadIdx.x >> 5, lane = threadIdx.x & 31;
    int row = blockIdx.x * 8 + warp;
    const float* zr = z + (size_t)row * D_;
    float s0 = 0.f, s1 = 0.f;
    for (int d = lane; d < D_; d += 32) {
        float zv = zr[d];
        s0 += zv * w[d*2 + 0];
        s1 += zv * w[d*2 + 1];
    }
    #pragma unroll
    for (int o = 16; o >= 1; o >>= 1) {
        s0 += __shfl_xor_sync(0xffffffffu, s0, o);
        s1 += __shfl_xor_sync(0xffffffffu, s1, o);
    }
    if (lane == 0) {
        out[row*2 + 0] = s0 + hb[0];
        out[row*2 + 1] = s1 + hb[1];
    }
}

// ---------------- host-side orchestration ----------------
static inline void launch_gemm(const __half* A, const __half* Bt, void* C,
                               int M, int N, int K, const float* bias, int relu,
                               int out_half)
{
    dim3 grid(N / 128, M / 128);
    tc_gemm_h_kernel<<<grid, 256, GEMM_SMEM_BYTES>>>(A, Bt, C, M, N, K, bias, relu, out_half);
}

extern "C" void kernel_launch(void* const* d_in, const int* in_sizes, int n_in,
                              void* d_out, int out_size)
{
    (void)in_sizes; (void)n_in; (void)out_size;
    const int*   tokens = (const int*)  d_in[0];
    const float* embed  = (const float*)d_in[1];
    const float* Wqr = (const float*)d_in[2];
    const float* Wqi = (const float*)d_in[3];
    const float* Wkr = (const float*)d_in[4];
    const float* Wki = (const float*)d_in[5];
    const float* Wv  = (const float*)d_in[6];
    const float* Wo  = (const float*)d_in[7];
    const float* bo  = (const float*)d_in[8];
    const float* W1  = (const float*)d_in[9];
    const float* b1  = (const float*)d_in[10];
    const float* W2  = (const float*)d_in[11];
    const float* b2  = (const float*)d_in[12];
    const float* g1  = (const float*)d_in[13];
    const float* be1 = (const float*)d_in[14];
    const float* g2  = (const float*)d_in[15];
    const float* be2 = (const float*)d_in[16];
    const float* hw  = (const float*)d_in[17];
    const float* hb  = (const float*)d_in[18];
    float* out = (float*)d_out;

    float *zr,*t0,*z1;
    __half *zrh,*acat,*qkvh,*ctxh,*z1h,*ffh,*b0h,*b1h,*wth;
    cudaGetSymbolAddress((void**)&zr,   g_zr);
    cudaGetSymbolAddress((void**)&zrh,  g_zrh);
    cudaGetSymbolAddress((void**)&acat, g_acat);
    cudaGetSymbolAddress((void**)&qkvh, g_qkvh);
    cudaGetSymbolAddress((void**)&ctxh, g_ctxh);
    cudaGetSymbolAddress((void**)&t0,   g_t0);
    cudaGetSymbolAddress((void**)&z1,   g_z1);
    cudaGetSymbolAddress((void**)&z1h,  g_z1h);
    cudaGetSymbolAddress((void**)&ffh,  g_ffh);
    cudaGetSymbolAddress((void**)&b0h,  g_b0h);
    cudaGetSymbolAddress((void**)&b1h,  g_b1h);
    cudaGetSymbolAddress((void**)&wth,  g_wth);

    cudaFuncSetAttribute(attn_tc_kernel, cudaFuncAttributeMaxDynamicSharedMemorySize,
                         ATTN_SMEM_BYTES);
    cudaFuncSetAttribute(tc_gemm_h_kernel, cudaFuncAttributeMaxDynamicSharedMemorySize,
                         GEMM_SMEM_BYTES);

    embed_pos_kernel<<<ROWS, 256>>>(tokens, embed, zr, acat);
    prep_weights_kernel<<<PREP_TOTAL, dim3(32, 8)>>>(Wqr, Wqi, Wkr, Wki, Wv, Wo, W1, W2,
                                                     b0h, b1h, wth);

    const size_t DD = (size_t)D_ * D_;
    const size_t DF = (size_t)D_ * DFF_;

    for (int l = 0; l < L_; l++) {
        __half* base = wth + (size_t)l * WT2_PER_LAYER;
        const __half* woT  = base;
        const __half* w1T  = base + DD;
        const __half* w2T  = base + DD + DF;
        const float* bo_l  = bo  + (size_t)l * D_;
        const float* b1_l  = b1  + (size_t)l * DFF_;
        const float* b2_l  = b2  + (size_t)l * D_;
        const float* g1_l  = g1  + (size_t)l * D_;
        const float* be1_l = be1 + (size_t)l * D_;
        const float* g2_l  = g2  + (size_t)l * D_;
        const float* be2_l = be2 + (size_t)l * D_;

        if (l == 0)
            launch_gemm(acat, b0h, qkvh, ROWS, QKV_N, 2 * D_, nullptr, 0, 1);
        else
            launch_gemm(zrh, b1h, qkvh, ROWS, QKV_N, D_, nullptr, 0, 1);

        dim3 ag(S_ / 128, H_, B_);
        attn_tc_kernel<<<ag, 256, ATTN_SMEM_BYTES>>>(qkvh, ctxh);

        launch_gemm(ctxh, woT, t0, ROWS, D_, D_, bo_l, 0, 0);
        ln_res_kernel<<<ROWS, 128>>>(zr, t0, g1_l, be1_l, z1, z1h);
        launch_gemm(z1h, w1T, ffh, ROWS, DFF_, D_, b1_l, 1, 1);
        launch_gemm(ffh, w2T, t0, ROWS, D_, DFF_, b2_l, 0, 0);
        ln_res_kernel<<<ROWS, 128>>>(z1, t0, g2_l, be2_l, zr, zrh);
    }

    head_kernel<<<ROWS / 8, 256>>>(zr, hw, hb, out);
}

// round 15
// speedup vs baseline: 1.2184x; 1.0691x over previous
#include <cuda_runtime.h>
#include <cuda_fp16.h>
#include <math.h>
#include <stdint.h>

#define B_   2
#define S_   2048
#define D_   512
#define H_   8
#define DK_  64
#define DFF_ 2048
#define L_   2
#define ROWS (B_*S_)   /* 4096 */

#define QKV_N  2560
#define QKV_LD 2560
#define AT_ST 72
#define ATTN_SMEM_BYTES (6 * 64 * AT_ST * 2)   /* 55296 */

/* 3-stage GEMM smem: per stage As(128x40)+Bs(128x40) halves */
#define GST      (128*40)
#define GSTAGE   (2*GST)
#define GEMM_SMEM_BYTES (3 * GSTAGE * 2)   /* 61440 */

// ---------------- scratch ----------------
__device__ float  g_zr  [ROWS * D_];
__device__ __half g_zrh [ROWS * D_];
__device__ __half g_acat[ROWS * 2 * D_];
__device__ __half g_qkvh[ROWS * QKV_LD];
__device__ __half g_ctxh[ROWS * D_];
__device__ float  g_t0  [ROWS * D_];
__device__ float  g_z1  [ROWS * D_];
__device__ __half g_z1h [ROWS * D_];
__device__ __half g_ffh [ROWS * DFF_];
__device__ __half g_b0h [QKV_N * 2 * D_];
__device__ __half g_b1h [QKV_N * D_];
#define WT2_PER_LAYER (D_*D_ + 2*D_*DFF_)
__device__ __half g_wth [L_ * WT2_PER_LAYER];

__device__ __forceinline__ uint32_t f22h(float a, float b) {
    __half2 h = __floats2half2_rn(a, b);
    return *(uint32_t*)&h;
}

#define MMA_F16(acc, a, b0, b1) \
    asm volatile("mma.sync.aligned.m16n8k16.row.col.f32.f16.f16.f32 " \
        "{%0,%1,%2,%3}, {%4,%5,%6,%7}, {%8,%9}, {%0,%1,%2,%3};" \
        : "+f"((acc)[0]), "+f"((acc)[1]), "+f"((acc)[2]), "+f"((acc)[3]) \
        : "r"((a)[0]), "r"((a)[1]), "r"((a)[2]), "r"((a)[3]), "r"(b0), "r"(b1))

__device__ __forceinline__ void cp_async16(void* smem, const void* gmem) {
    uint32_t s = (uint32_t)__cvta_generic_to_shared(smem);
    asm volatile("cp.async.cg.shared.global [%0], [%1], 16;" :: "r"(s), "l"(gmem));
}
#define CP_COMMIT() asm volatile("cp.async.commit_group;" ::: "memory")
#define CP_WAIT0()  asm volatile("cp.async.wait_group 0;"  ::: "memory")
#define CP_WAIT1()  asm volatile("cp.async.wait_group 1;"  ::: "memory")

__device__ __forceinline__ void ldmx4(uint32_t* r, uint32_t addr) {
    asm volatile("ldmatrix.sync.aligned.m8n8.x4.shared.b16 {%0,%1,%2,%3}, [%4];"
        : "=r"(r[0]), "=r"(r[1]), "=r"(r[2]), "=r"(r[3]) : "r"(addr));
}
__device__ __forceinline__ void ldmx4t(uint32_t* r, uint32_t addr) {
    asm volatile("ldmatrix.sync.aligned.m8n8.x4.trans.shared.b16 {%0,%1,%2,%3}, [%4];"
        : "=r"(r[0]), "=r"(r[1]), "=r"(r[2]), "=r"(r[3]) : "r"(addr));
}

// ---------------- all-fp16 3-stage pipelined tensor-core GEMM ----------------
__global__ void __launch_bounds__(256) tc_gemm_h_kernel(
    const __half* __restrict__ A, const __half* __restrict__ Bt, void* __restrict__ C,
    int M, int N, int K, const float* __restrict__ bias, int relu, int out_half)
{
    extern __shared__ __half gsm[];

    const int tid  = threadIdx.x;
    const int wid  = tid >> 5, lane = tid & 31;
    const int gid  = lane >> 2, tig = lane & 3;
    const int wy   = wid >> 2, wx = wid & 3;
    const int bm   = blockIdx.y, bn = blockIdx.x;

    const __half* Ab = A  + (size_t)bm * 128 * K;
    const __half* Bb = Bt + (size_t)bn * 128 * K;

    const int lr = tid >> 2;
    const int c8 = (tid & 3) * 8;

    const uint32_t sm_sh = (uint32_t)__cvta_generic_to_shared(gsm);
    const uint32_t a_lo  = (uint32_t)(lane & 15) * 40 + ((lane >> 4) << 3);
    const uint32_t b4_lo = ((uint32_t)(lane & 7) + ((lane >> 4) << 3)) * 40 + ((lane >> 3) & 1) * 8;

    float acc[4][4][4];
    #pragma unroll
    for (int i = 0; i < 4; i++)
        #pragma unroll
        for (int j = 0; j < 4; j++)
            #pragma unroll
            for (int r = 0; r < 4; r++) acc[i][j][r] = 0.f;

    const int nch = K >> 5;

    #pragma unroll
    for (int pc = 0; pc < 2; pc++) {
        if (pc < nch) {
            __half* As = gsm + pc * GSTAGE;
            __half* Bs = As + GST;
            const __half* a0 = Ab + (size_t)lr * K + pc * 32 + c8;
            const __half* b0 = Bb + (size_t)lr * K + pc * 32 + c8;
            cp_async16(&As[(size_t)lr * 40 + c8],        a0);
            cp_async16(&As[(size_t)(lr + 64) * 40 + c8], a0 + (size_t)64 * K);
            cp_async16(&Bs[(size_t)lr * 40 + c8],        b0);
            cp_async16(&Bs[(size_t)(lr + 64) * 40 + c8], b0 + (size_t)64 * K);
        }
        CP_COMMIT();
    }

    for (int c = 0; c < nch; c++) {
        CP_WAIT1();
        __syncthreads();
        {
            if (c + 2 < nch) {
                const int sn = (c + 2) % 3;
                __half* As = gsm + sn * GSTAGE;
                __half* Bs = As + GST;
                const int kg = (c + 2) * 32 + c8;
                const __half* a0 = Ab + (size_t)lr * K + kg;
                const __half* b0 = Bb + (size_t)lr * K + kg;
                cp_async16(&As[(size_t)lr * 40 + c8],        a0);
                cp_async16(&As[(size_t)(lr + 64) * 40 + c8], a0 + (size_t)64 * K);
                cp_async16(&Bs[(size_t)lr * 40 + c8],        b0);
                cp_async16(&Bs[(size_t)(lr + 64) * 40 + c8], b0 + (size_t)64 * K);
            }
            CP_COMMIT();
        }
        const int s = c % 3;
        const uint32_t abase = sm_sh + (uint32_t)s * GSTAGE * 2;
        const uint32_t bbase = abase + GST * 2;
        #pragma unroll
        for (int ks = 0; ks < 2; ks++) {
            uint32_t af[4][4];
            #pragma unroll
            for (int mf = 0; mf < 4; mf++)
                ldmx4(af[mf], abase + ((uint32_t)(wy*64 + mf*16) * 40 + ks*16 + a_lo) * 2);
            uint32_t bf[2][4];
            #pragma unroll
            for (int p = 0; p < 2; p++)
                ldmx4(bf[p], bbase + ((uint32_t)(wx*32 + p*16) * 40 + ks*16 + b4_lo) * 2);
            #pragma unroll
            for (int mf = 0; mf < 4; mf++)
                #pragma unroll
                for (int p = 0; p < 2; p++) {
                    MMA_F16(acc[mf][2*p    ], af[mf], bf[p][0], bf[p][1]);
                    MMA_F16(acc[mf][2*p + 1], af[mf], bf[p][2], bf[p][3]);
                }
        }
    }

    float2 bsv[4];
    if (bias) {
        #pragma unroll
        for (int nf = 0; nf < 4; nf++) {
            const int col = bn * 128 + wx * 32 + nf * 8 + tig * 2;
            bsv[nf] = *(const float2*)(bias + col);
        }
    }
    #pragma unroll
    for (int mf = 0; mf < 4; mf++) {
        const int row = bm * 128 + wy * 64 + mf * 16 + gid;
        #pragma unroll
        for (int nf = 0; nf < 4; nf++) {
            const int col = bn * 128 + wx * 32 + nf * 8 + tig * 2;
            #pragma unroll
            for (int half = 0; half < 2; half++) {
                const int r = row + half * 8;
                float vx = acc[mf][nf][half*2 + 0];
                float vy = acc[mf][nf][half*2 + 1];
                if (bias) { vx += bsv[nf].x; vy += bsv[nf].y; }
                if (relu) { vx = fmaxf(vx, 0.f); vy = fmaxf(vy, 0.f); }
                if (out_half) {
                    *(uint32_t*)((__half*)C + (size_t)r * N + col) = f22h(vx, vy);
                } else {
                    *(float2*)((float*)C + (size_t)r * N + col) = make_float2(vx, vy);
                }
            }
        }
    }
}

// ---------------- batched weight prep ----------------
#define PREP_A0   2560
#define PREP_A1   (PREP_A0 + 1280)
#define PREP_TPL  (256 + 1024 + 1024)
#define PREP_TOTAL (PREP_A1 + 2 * PREP_TPL)

__device__ __forceinline__ void prep_assemble(
    const float* Wqr, const float* Wqi, const float* Wkr, const float* Wki,
    const float* Wv, __half* out, int Kfull, int t, float sm[32][33])
{
    const int ntk = Kfull >> 5;
    const int k0 = (t % ntk) * 32, n0 = (t / ntk) * 32;
    const int blk  = n0 >> 9;
    const int half = k0 >> 9;
    const int ks   = k0 & 511;
    const int ns   = n0 & 511;

    const float* src = Wv;
    float sign = 1.f;
    bool zero = false;
    if      (blk == 0) { if (half == 0) src = Wqr; else { src = Wqi; sign = -1.f; } }
    else if (blk == 1) { if (half == 0) src = Wqi; else   src = Wqr; }
    else if (blk == 2) { if (half == 0) src = Wkr; else { src = Wki; sign = -1.f; } }
    else if (blk == 3) { if (half == 0) src = Wki; else   src = Wkr; }
    else               { if (half == 0) src = Wv;  else   zero = true; }

    #pragma unroll
    for (int i = threadIdx.y; i < 32; i += 8)
        sm[i][threadIdx.x] = zero ? 0.f : src[(size_t)(ks + i) * 512 + ns + threadIdx.x];
    __syncthreads();
    #pragma unroll
    for (int i = threadIdx.y; i < 32; i += 8)
        out[(size_t)(n0 + i) * Kfull + k0 + threadIdx.x] =
            __float2half_rn(sign * sm[threadIdx.x][i]);
}

__device__ __forceinline__ void prep_transpose(
    const float* in, __half* out, int R, int Cc, int t, float sm[32][33])
{
    const int ntc = Cc >> 5;
    const int c0 = (t % ntc) * 32, r0 = (t / ntc) * 32;
    #pragma unroll
    for (int i = threadIdx.y; i < 32; i += 8)
        sm[i][threadIdx.x] = in[(size_t)(r0 + i) * Cc + c0 + threadIdx.x];
    __syncthreads();
    #pragma unroll
    for (int i = threadIdx.y; i < 32; i += 8)
        out[(size_t)(c0 + i) * R + r0 + threadIdx.x] = __float2half_rn(sm[threadIdx.x][i]);
}

__global__ void __launch_bounds__(256) prep_weights_kernel(
    const float* __restrict__ Wqr, const float* __restrict__ Wqi,
    const float* __restrict__ Wkr, const float* __restrict__ Wki,
    const float* __restrict__ Wv,  const float* __restrict__ Wo,
    const float* __restrict__ W1,  const float* __restrict__ W2,
    __half* __restrict__ b0h, __half* __restrict__ b1h, __half* __restrict__ wth)
{
    __shared__ float sm[32][33];
    const size_t DD = (size_t)D_ * D_;
    const size_t DF = (size_t)D_ * DFF_;
    int bid = blockIdx.x;

    if (bid < PREP_A0) {
        prep_assemble(Wqr, Wqi, Wkr, Wki, Wv, b0h, 2 * D_, bid, sm);
        return;
    }
    bid -= PREP_A0;
    if (bid < 1280) {
        prep_assemble(Wqr + DD, Wqi + DD, Wkr + DD, Wki + DD, Wv + DD, b1h, D_, bid, sm);
        return;
    }
    bid -= 1280;
    const int l = bid / PREP_TPL;
    int t = bid % PREP_TPL;
    __half* base = wth + (size_t)l * WT2_PER_LAYER;
    if (t < 256)        { prep_transpose(Wo + l*DD, base,           D_,   D_,   t,        sm); }
    else if (t < 1280)  { prep_transpose(W1 + l*DF, base + DD,      D_,   DFF_, t - 256,  sm); }
    else                { prep_transpose(W2 + l*DF, base + DD + DF, DFF_, D_,   t - 1280, sm); }
}

// ---------------- fused embedding + positional imag ----------------
__global__ void __launch_bounds__(256) embed_pos_kernel(
    const int* __restrict__ tok, const float* __restrict__ emb,
    float* __restrict__ zr, __half* __restrict__ acat)
{
    int row = blockIdx.x;
    int tid = threadIdx.x;
    if (tid < 128) {
        int t = tok[row];
        int c4 = tid * 4;
        float4 v = *(const float4*)(emb + (size_t)t * D_ + c4);
        *(float4*)(zr + (size_t)row * D_ + c4) = v;
        *(uint2*)(acat + (size_t)row * 2 * D_ + c4) =
            make_uint2(f22h(v.x, v.y), f22h(v.z, v.w));
    } else {
        int s = row & (S_ - 1);
        int j2 = (tid - 128) * 2;
        float f0 = __expf(-((float)(j2    ) * (1.0f/256.0f)) * 9.2103403719761836f);
        float f1 = __expf(-((float)(j2 + 1) * (1.0f/256.0f)) * 9.2103403719761836f);
        float v0 = sinf((float)s * f0);
        float v1 = sinf((float)s * f1);
        *(uint2*)(acat + (size_t)row * 2 * D_ + D_ + j2 * 2) =
            make_uint2(f22h(v0, v0), f22h(v1, v1));
    }
}

// ---------------- fp16 TC complex-hybrid flash attention ----------------
// Same as R14 winner, but __launch_bounds__(256, 2): cap regs at 128 so
// 2 CTAs co-reside per SM (occupancy 12.5% -> 25%, single wave for grid=256).
__global__ void __launch_bounds__(256, 2) attn_tc_kernel(
    const __half* __restrict__ QKV, __half* __restrict__ Out)
{
    extern __shared__ __half smh[];
    __half (*bKr)[AT_ST] = (__half(*)[AT_ST])smh;
    __half (*bKi)[AT_ST] = bKr + 128;
    __half (*bV )[AT_ST] = bKi + 128;

    const int q0 = blockIdx.x * 128;
    const int h  = blockIdx.y;
    const int b  = blockIdx.z;
    const int tid  = threadIdx.x;
    const int wid  = tid >> 5, lane = tid & 31;
    const int gid  = lane >> 2, tig = lane & 3;
    const int wrow = wid * 16;
    const size_t baseq = ((size_t)b * S_) * QKV_LD + (size_t)h * DK_;
    const size_t baseo = ((size_t)b * S_) * D_     + (size_t)h * DK_;

    const uint32_t kr_sh = (uint32_t)__cvta_generic_to_shared(bKr);
    const uint32_t ki_sh = (uint32_t)__cvta_generic_to_shared(bKi);
    const uint32_t v_sh  = (uint32_t)__cvta_generic_to_shared(bV);

    for (int i = tid; i < 128*8; i += 256) {
        int r = i >> 3, c8 = (i & 7) * 8;
        const __half* qrow = QKV + baseq + (size_t)(q0 + r) * QKV_LD + c8;
        *(uint4*)&bKr[r][c8] = *(const uint4*)(qrow);
        *(uint4*)&bKi[r][c8] = *(const uint4*)(qrow + 512);
    }
    __syncthreads();

    uint32_t aQr[4][4], aQi[4][4];
    {
        const uint32_t ro = ((uint32_t)(wrow + (lane & 15)) * AT_ST + ((lane >> 4) << 3)) * 2;
        #pragma unroll
        for (int k = 0; k < 4; k++) {
            ldmx4(aQr[k], kr_sh + ro + k * 32);
            ldmx4(aQi[k], ki_sh + ro + k * 32);
        }
    }
    __syncthreads();

    float o[8][4];
    #pragma unroll
    for (int n = 0; n < 8; n++)
        #pragma unroll
        for (int e = 0; e < 4; e++) o[n][e] = 0.f;
    float l0 = 0.f, l1 = 0.f;

    const uint32_t kb4_lo = ((uint32_t)(lane & 7) + ((lane >> 4) << 3)) * AT_ST
                          + ((lane >> 3) & 1) * 8;
    const uint32_t vb4_lo = (uint32_t)(lane & 15) * AT_ST + ((lane >> 4) << 3);

    {
        for (int i = tid; i < 64*8; i += 256) {
            int r = i >> 3, c8 = (i & 7) * 8;
            const __half* krow = QKV + baseq + (size_t)r * QKV_LD + c8;
            cp_async16(&bKr[r][c8], krow + 1024);
            cp_async16(&bKi[r][c8], krow + 1536);
            cp_async16(&bV [r][c8], krow + 2048);
        }
        CP_COMMIT();
    }

    const int NT = S_ / 64;
    for (int ti = 0; ti < NT; ti++) {
        CP_WAIT0();
        __syncthreads();
        if (ti + 1 < NT) {
            const int sn = (ti + 1) & 1;
            const int kt = (ti + 1) * 64;
            for (int i = tid; i < 64*8; i += 256) {
                int r = i >> 3, c8 = (i & 7) * 8;
                const __half* krow = QKV + baseq + (size_t)(kt + r) * QKV_LD + c8;
                cp_async16(&bKr[sn*64 + r][c8], krow + 1024);
                cp_async16(&bKi[sn*64 + r][c8], krow + 1536);
                cp_async16(&bV [sn*64 + r][c8], krow + 2048);
            }
            CP_COMMIT();
        }
        const int s = ti & 1;
        const uint32_t soff = (uint32_t)(s * 64) * AT_ST * 2;

        float srf[8][4], sif[8][4];
        #pragma unroll
        for (int n = 0; n < 8; n++)
            #pragma unroll
            for (int e = 0; e < 4; e++) { srf[n][e] = 0.f; sif[n][e] = 0.f; }

        #pragma unroll
        for (int k = 0; k < 4; k++) {
            #pragma unroll
            for (int p = 0; p < 4; p++) {
                const uint32_t off = soff + ((uint32_t)(p * 16) * AT_ST + k * 16 + kb4_lo) * 2;
                uint32_t br[4], bi[4];
                ldmx4(br, kr_sh + off);
                ldmx4(bi, ki_sh + off);
                MMA_F16(srf[2*p    ], aQr[k], br[0], br[1]);
                MMA_F16(srf[2*p    ], aQi[k], bi[0], bi[1]);
                MMA_F16(sif[2*p    ], aQi[k], br[0], br[1]);
                uint32_t x0 = bi[0] ^ 0x80008000u, x1 = bi[1] ^ 0x80008000u;
                MMA_F16(sif[2*p    ], aQr[k], x0, x1);
                MMA_F16(srf[2*p + 1], aQr[k], br[2], br[3]);
                MMA_F16(srf[2*p + 1], aQi[k], bi[2], bi[3]);
                MMA_F16(sif[2*p + 1], aQi[k], br[2], br[3]);
                uint32_t x2 = bi[2] ^ 0x80008000u, x3 = bi[3] ^ 0x80008000u;
                MMA_F16(sif[2*p + 1], aQr[k], x2, x3);
            }
        }

        float psum0 = 0.f, psum1 = 0.f;
        #pragma unroll
        for (int n = 0; n < 8; n++) {
            #pragma unroll
            for (int e = 0; e < 4; e++) {
                float a = srf[n][e], c = sif[n][e];
                float m2 = fmaf(a, a, c * c);
                float y  = rsqrtf(m2);
                float sc = y * fmaf(0.015625f, m2, 0.0375f * a);
                sc = (m2 == 0.f) ? 0.0375f : sc;
                float p = __expf(sc);
                srf[n][e] = p;
                if (e < 2) psum0 += p; else psum1 += p;
            }
        }
        psum0 += __shfl_xor_sync(0xffffffffu, psum0, 1);
        psum0 += __shfl_xor_sync(0xffffffffu, psum0, 2);
        psum1 += __shfl_xor_sync(0xffffffffu, psum1, 1);
        psum1 += __shfl_xor_sync(0xffffffffu, psum1, 2);
        l0 += psum0; l1 += psum1;

        #pragma unroll
        for (int kc = 0; kc < 4; kc++) {
            uint32_t ap[4];
            ap[0] = f22h(srf[2*kc  ][0], srf[2*kc  ][1]);
            ap[1] = f22h(srf[2*kc  ][2], srf[2*kc  ][3]);
            ap[2] = f22h(srf[2*kc+1][0], srf[2*kc+1][1]);
            ap[3] = f22h(srf[2*kc+1][2], srf[2*kc+1][3]);
            #pragma unroll
            for (int p = 0; p < 4; p++) {
                const uint32_t off = soff + ((uint32_t)(kc * 16) * AT_ST + p * 16 + vb4_lo) * 2;
                uint32_t bv[4];
                ldmx4t(bv, v_sh + off);
                MMA_F16(o[2*p    ], ap, bv[0], bv[1]);
                MMA_F16(o[2*p + 1], ap, bv[2], bv[3]);
            }
        }
    }

    const float inv0 = 1.0f / l0;
    const float inv1 = 1.0f / l1;
    #pragma unroll
    for (int n = 0; n < 8; n++) {
        const int col = n * 8 + 2 * tig;
        *(uint32_t*)(Out + baseo + (size_t)(q0 + wrow + gid    ) * D_ + col) =
            f22h(o[n][0] * inv0, o[n][1] * inv0);
        *(uint32_t*)(Out + baseo + (size_t)(q0 + wrow + gid + 8) * D_ + col) =
            f22h(o[n][2] * inv1, o[n][3] * inv1);
    }
}

// ---------------- fused residual + layernorm ----------------
__global__ void __launch_bounds__(128) ln_res_kernel(
    const float* __restrict__ x, const float* __restrict__ r,
    const float* __restrict__ g, const float* __restrict__ be,
    float* __restrict__ outf, __half* __restrict__ outh)
{
    __shared__ float red[8];
    int row = blockIdx.x, tid = threadIdx.x;
    float4 xv = *(const float4*)(x + (size_t)row * D_ + tid * 4);
    float4 rv = *(const float4*)(r + (size_t)row * D_ + tid * 4);
    float v0 = xv.x + rv.x, v1 = xv.y + rv.y, v2 = xv.z + rv.z, v3 = xv.w + rv.w;
    float s  = v0 + v1 + v2 + v3;
    float s2 = v0*v0 + v1*v1 + v2*v2 + v3*v3;
    #pragma unroll
    for (int o = 16; o >= 1; o >>= 1) {
        s  += __shfl_xor_sync(0xffffffffu, s,  o);
        s2 += __shfl_xor_sync(0xffffffffu, s2, o);
    }
    int warp = tid >> 5, lane = tid & 31;
    if (lane == 0) { red[warp] = s; red[4 + warp] = s2; }
    __syncthreads();
    s  = red[0] + red[1] + red[2] + red[3];
    s2 = red[4] + red[5] + red[6] + red[7];
    float mu  = s  * (1.0f / D_);
    float var = s2 * (1.0f / D_) - mu * mu;
    float inv = rsqrtf(var + 1e-5f);
    float4 gv = *(const float4*)(g  + tid * 4);
    float4 bv = *(const float4*)(be + tid * 4);
    float4 o4;
    o4.x = (v0 - mu) * inv * gv.x + bv.x;
    o4.y = (v1 - mu) * inv * gv.y + bv.y;
    o4.z = (v2 - mu) * inv * gv.z + bv.z;
    o4.w = (v3 - mu) * inv * gv.w + bv.w;
    *(float4*)(outf + (size_t)row * D_ + tid * 4) = o4;
    *(uint2*)(outh + (size_t)row * D_ + tid * 4) =
        make_uint2(f22h(o4.x, o4.y), f22h(o4.z, o4.w));
}

// ---------------- classification head ----------------
__global__ void __launch_bounds__(256) head_kernel(
    const float* __restrict__ z, const float* __restrict__ w,
    const float* __restrict__ hb, float* __restrict__ out)
{
    int warp = threadIdx.x >> 5, lane = threadIdx.x & 31;
    int row = blockIdx.x * 8 + warp;
    const float* zr = z + (size_t)row * D_;
    float s0 = 0.f, s1 = 0.f;
    for (int d = lane; d < D_; d += 32) {
        float zv = zr[d];
        s0 += zv * w[d*2 + 0];
        s1 += zv * w[d*2 + 1];
    }
    #pragma unroll
    for (int o = 16; o >= 1; o >>= 1) {
        s0 += __shfl_xor_sync(0xffffffffu, s0, o);
        s1 += __shfl_xor_sync(0xffffffffu, s1, o);
    }
    if (lane == 0) {
        out[row*2 + 0] = s0 + hb[0];
        out[row*2 + 1] = s1 + hb[1];
    }
}

// ---------------- host-side orchestration ----------------
static inline void launch_gemm(const __half* A, const __half* Bt, void* C,
                               int M, int N, int K, const float* bias, int relu,
                               int out_half)
{
    dim3 grid(N / 128, M / 128);
    tc_gemm_h_kernel<<<grid, 256, GEMM_SMEM_BYTES>>>(A, Bt, C, M, N, K, bias, relu, out_half);
}

extern "C" void kernel_launch(void* const* d_in, const int* in_sizes, int n_in,
                              void* d_out, int out_size)
{
    (void)in_sizes; (void)n_in; (void)out_size;
    const int*   tokens = (const int*)  d_in[0];
    const float* embed  = (const float*)d_in[1];
    const float* Wqr = (const float*)d_in[2];
    const float* Wqi = (const float*)d_in[3];
    const float* Wkr = (const float*)d_in[4];
    const float* Wki = (const float*)d_in[5];
    const float* Wv  = (const float*)d_in[6];
    const float* Wo  = (const float*)d_in[7];
    const float* bo  = (const float*)d_in[8];
    const float* W1  = (const float*)d_in[9];
    const float* b1  = (const float*)d_in[10];
    const float* W2  = (const float*)d_in[11];
    const float* b2  = (const float*)d_in[12];
    const float* g1  = (const float*)d_in[13];
    const float* be1 = (const float*)d_in[14];
    const float* g2  = (const float*)d_in[15];
    const float* be2 = (const float*)d_in[16];
    const float* hw  = (const float*)d_in[17];
    const float* hb  = (const float*)d_in[18];
    float* out = (float*)d_out;

    float *zr,*t0,*z1;
    __half *zrh,*acat,*qkvh,*ctxh,*z1h,*ffh,*b0h,*b1h,*wth;
    cudaGetSymbolAddress((void**)&zr,   g_zr);
    cudaGetSymbolAddress((void**)&zrh,  g_zrh);
    cudaGetSymbolAddress((void**)&acat, g_acat);
    cudaGetSymbolAddress((void**)&qkvh, g_qkvh);
    cudaGetSymbolAddress((void**)&ctxh, g_ctxh);
    cudaGetSymbolAddress((void**)&t0,   g_t0);
    cudaGetSymbolAddress((void**)&z1,   g_z1);
    cudaGetSymbolAddress((void**)&z1h,  g_z1h);
    cudaGetSymbolAddress((void**)&ffh,  g_ffh);
    cudaGetSymbolAddress((void**)&b0h,  g_b0h);
    cudaGetSymbolAddress((void**)&b1h,  g_b1h);
    cudaGetSymbolAddress((void**)&wth,  g_wth);

    cudaFuncSetAttribute(attn_tc_kernel, cudaFuncAttributeMaxDynamicSharedMemorySize,
                         ATTN_SMEM_BYTES);
    cudaFuncSetAttribute(tc_gemm_h_kernel, cudaFuncAttributeMaxDynamicSharedMemorySize,
                         GEMM_SMEM_BYTES);

    embed_pos_kernel<<<ROWS, 256>>>(tokens, embed, zr, acat);
    prep_weights_kernel<<<PREP_TOTAL, dim3(32, 8)>>>(Wqr, Wqi, Wkr, Wki, Wv, Wo, W1, W2,
                                                     b0h, b1h, wth);

    const size_t DD = (size_t)D_ * D_;
    const size_t DF = (size_t)D_ * DFF_;

    for (int l = 0; l < L_; l++) {
        __half* base = wth + (size_t)l * WT2_PER_LAYER;
        const __half* woT  = base;
        const __half* w1T  = base + DD;
        const __half* w2T  = base + DD + DF;
        const float* bo_l  = bo  + (size_t)l * D_;
        const float* b1_l  = b1  + (size_t)l * DFF_;
        const float* b2_l  = b2  + (size_t)l * D_;
        const float* g1_l  = g1  + (size_t)l * D_;
        const float* be1_l = be1 + (size_t)l * D_;
        const float* g2_l  = g2  + (size_t)l * D_;
        const float* be2_l = be2 + (size_t)l * D_;

        if (l == 0)
            launch_gemm(acat, b0h, qkvh, ROWS, QKV_N, 2 * D_, nullptr, 0, 1);
        else
            launch_gemm(zrh, b1h, qkvh, ROWS, QKV_N, D_, nullptr, 0, 1);

        dim3 ag(S_ / 128, H_, B_);
        attn_tc_kernel<<<ag, 256, ATTN_SMEM_BYTES>>>(qkvh, ctxh);

        launch_gemm(ctxh, woT, t0, ROWS, D_, D_, bo_l, 0, 0);
        ln_res_kernel<<<ROWS, 128>>>(zr, t0, g1_l, be1_l, z1, z1h);
        launch_gemm(z1h, w1T, ffh, ROWS, DFF_, D_, b1_l, 1, 1);
        launch_gemm(ffh, w2T, t0, ROWS, D_, DFF_, b2_l, 0, 0);
        ln_res_kernel<<<ROWS, 128>>>(z1, t0, g2_l, be2_l, zr, zrh);
    }

    head_kernel<<<ROWS / 8, 256>>>(zr, hw, hb, out);
}